// round 12
// baseline (speedup 1.0000x reference)
#include <cuda_runtime.h>
#include <cuda_bf16.h>
#include <math.h>
#include <stdint.h>

typedef unsigned int u32; typedef unsigned long long u64;

__device__ float g_cam0 [64*128*784];
__device__ float g_cam1 [64*128*196];
__device__ float g_cam2 [64*128*49];
__device__ float g_linkpart[320*16384];
__device__ u32   g_whi[229376];   // pre-split, pre-swizzled W tiles (bf16x2 hi)
__device__ u32   g_wlo[229376];   // residual lo
// pre-split SW128 link tiles, written by stats_kernel:
__device__ u32 g_l0a_hi[1048576], g_l0a_lo[1048576];  // cam0 pooled+norm  [b*4+c][4096]
__device__ u32 g_l0b_hi[1048576], g_l0b_lo[1048576];  // cam1 norm         [b*4+c][4096]
__device__ u32 g_l1a_hi[262144],  g_l1a_lo[262144];   // cam1 pooled+norm  [b][4096]
__device__ u32 g_l1b_hi[262144],  g_l1b_lo[262144];   // cam2 norm         [b][4096]

__device__ __forceinline__ u32 smem_u32(const void* p){u32 a;asm("{ .reg .u64 t; cvta.to.shared.u64 t, %1; cvt.u32.u64 %0, t; }":"=r"(a):"l"(p));return a;}
#define SW128(o) ((o) ^ (((o) >> 3) & 0x70))
__device__ __forceinline__ void sts32(u32 a,u32 v){asm volatile("st.shared.b32 [%0], %1;"::"r"(a),"r"(v));}
__device__ __forceinline__ u32 cvt_bf16x2(float a,float b){u32 r;asm("cvt.rn.satfinite.bf16x2.f32 %0, %1, %2;":"=r"(r):"f"(b),"f"(a));return r;}
__device__ __forceinline__ void split_pair(float a,float b,u32& hi,u32& lo){
    hi = cvt_bf16x2(a,b);
    float h0 = __uint_as_float(hi<<16);
    float h1 = __uint_as_float(hi&0xffff0000u);
    lo = cvt_bf16x2(a-h0, b-h1);
}
__device__ __forceinline__ void ldmx4(u32& r0,u32& r1,u32& r2,u32& r3,u32 a){
    asm volatile("ldmatrix.sync.aligned.m8n8.x4.shared.b16 {%0,%1,%2,%3}, [%4];":"=r"(r0),"=r"(r1),"=r"(r2),"=r"(r3):"r"(a));
}
__device__ __forceinline__ void ldmx2(u32& r0,u32& r1,u32 a){
    asm volatile("ldmatrix.sync.aligned.m8n8.x2.shared.b16 {%0,%1}, [%2];":"=r"(r0),"=r"(r1):"r"(a));
}
__device__ __forceinline__ void mma16816(float* c,const u32* a,const u32* b){
    asm volatile("mma.sync.aligned.m16n8k16.row.col.f32.bf16.bf16.f32 {%0,%1,%2,%3},{%4,%5,%6,%7},{%8,%9},{%0,%1,%2,%3};"
    :"+f"(c[0]),"+f"(c[1]),"+f"(c[2]),"+f"(c[3])
    :"r"(a[0]),"r"(a[1]),"r"(a[2]),"r"(a[3]),"r"(b[0]),"r"(b[1]));
}
__device__ __forceinline__ void cpasync16(u32 dst,const void* src){
    asm volatile("cp.async.cg.shared.global [%0], [%1], 16;"::"r"(dst),"l"(src));
}
__device__ __forceinline__ void cpasync_commit(){asm volatile("cp.async.commit_group;":::"memory");}
__device__ __forceinline__ void cpasync_wait0(){asm volatile("cp.async.wait_group 0;":::"memory");}

// ---- W pre-split into swizzled tile images: [level][chunk][4096 u32] ----
__global__ void __launch_bounds__(256) wsplit_kernel(const float* __restrict__ w0,const float* __restrict__ w1,const float* __restrict__ w2){
    int idx = blockIdx.x*256 + threadIdx.x;
    const float* w; int base, CP;
    if (idx < 32768)      { w=w0; base=0;     CP=256;  }
    else if (idx < 98304) { w=w1; base=32768; CP=512;  }
    else if (idx < 229376){ w=w2; base=98304; CP=1024; }
    else return;
    int local = idx - base;
    int r  = local / CP;
    int ck = local % CP;
    int chunk = ck >> 5;
    int kp    = ck & 31;
    float2 v = ((const float2*)w)[(size_t)r*CP + chunk*32 + kp];
    u32 hi,lo; split_pair(v.x,v.y,hi,lo);
    u32 dst = (u32)base + chunk*4096u + (SW128((u32)(r*128 + kp*4))>>2);
    g_whi[dst]=hi; g_wlo[dst]=lo;
}

// ======================================================================
// mma.sync bf16-split CAM GEMM — R9 config (proven best).
// ======================================================================
#define SM_AHI 0
#define SM_ALO 16384
#define SM_BHI 32768
#define SM_BLO 47104
#define SM_BUF 61440
#define GEMM_SMEM_BYTES 122880

__global__ void __launch_bounds__(256,1) mma_cam_gemm(const float* __restrict__ f0,const float* __restrict__ f1,const float* __restrict__ f2){
    extern __shared__ char smem[];
    const u32 sb = smem_u32(smem);
    const int tid = threadIdx.x, w = tid>>5, lane = tid&31;

    const int blk = blockIdx.x;
    int lvl,b,hw0,pair=0;
    if (blk < 32)        { lvl=2; pair=blk; b=0; hw0=0; }
    else if (blk < 160)  { lvl=1; int i=blk-32;  b=i>>1; hw0=(i&1)*112; }
    else                 { lvl=0; int i=blk-160; b=i/7;  hw0=(i%7)*112; }

    const float* fmap; float* cam; int C,HW,CHUNKS,wbase;
    if (lvl==0)      { fmap=f0; cam=g_cam0; C=512;  HW=784; CHUNKS=8;  wbase=0; }
    else if (lvl==1) { fmap=f1; cam=g_cam1; C=1024; HW=196; CHUNKS=16; wbase=32768; }
    else             { fmap=f2; cam=g_cam2; C=2048; HW=49;  CHUNKS=32; wbase=98304; }
    int nmax = HW - hw0; if (nmax > 112) nmax = 112;

    const int wy = w&3, wx = w>>2;
    const int nl  = lane>>2;
    const int kp4 = lane&3;
    const int g0n = w*8 + nl;
    const int g1n = (w+8)*8 + nl;
    const bool hasg1 = (w < 6);

    const float* fsrc[2]; bool okg[2];
    #pragma unroll
    for (int g=0; g<2; g++){
        int n = g ? g1n : g0n;
        bool valid = (g==0) || hasg1;
        int bq, j;
        if (lvl==2){ int q = (n>=56)?1:0; j = n - q*56; bq = pair*2 + q; valid = valid && (j<49); }
        else       { j = n; bq = b; valid = valid && (n < nmax); }
        fsrc[g] = fmap + (size_t)bq*C*HW + hw0 + j;
        okg[g]  = valid;
    }

    float pf[2][8][2];
    #define LOADB(CH) do { \
        int _c0 = (CH)*64; \
        _Pragma("unroll") \
        for (int _g=0;_g<2;_g++){ \
            if (_g==1 && !hasg1) break; \
            const float* _p = fsrc[_g] + (size_t)_c0*HW; \
            bool _ok = okg[_g]; \
            _Pragma("unroll") \
            for (int _i=0;_i<8;_i++){ \
                int _kp = _i*4 + kp4; \
                const float* _q = _p + (size_t)(2*_kp)*HW; \
                pf[_g][_i][0] = _ok ? _q[0]  : 0.0f; \
                pf[_g][_i][1] = _ok ? _q[HW] : 0.0f; \
            } \
        } \
    } while(0)

    #define STSB(BUFO) do { \
        _Pragma("unroll") \
        for (int _g=0;_g<2;_g++){ \
            if (_g==1 && !hasg1) break; \
            int _n = _g ? g1n : g0n; \
            _Pragma("unroll") \
            for (int _i=0;_i<8;_i++){ \
                int _kp = _i*4 + kp4; \
                u32 _hi,_lo; split_pair(pf[_g][_i][0], pf[_g][_i][1], _hi, _lo); \
                u32 _off = SW128((u32)(_n*128 + _kp*4)); \
                sts32(sb+(BUFO)+SM_BHI+_off, _hi); \
                sts32(sb+(BUFO)+SM_BLO+_off, _lo); \
            } \
        } \
    } while(0)

    #define CPA(CH,BUFO) do { \
        const char* _sH = (const char*)(g_whi + wbase + (CH)*4096) + tid*16; \
        const char* _sL = (const char*)(g_wlo + wbase + (CH)*4096) + tid*16; \
        u32 _dH = sb + (BUFO) + SM_AHI + tid*16; \
        u32 _dL = sb + (BUFO) + SM_ALO + tid*16; \
        _Pragma("unroll") \
        for (int _i=0;_i<4;_i++){ \
            cpasync16(_dH + _i*4096, _sH + _i*4096); \
            cpasync16(_dL + _i*4096, _sL + _i*4096); \
        } \
    } while(0)

    float acc[2][7][4];
    #pragma unroll
    for (int mt=0;mt<2;mt++)
        #pragma unroll
        for (int nt=0;nt<7;nt++)
            #pragma unroll
            for (int q=0;q<4;q++) acc[mt][nt][q]=0.f;

    CPA(0, 0u);
    cpasync_commit();
    LOADB(0);

    for (int chunk=0; chunk<CHUNKS; chunk++){
        const u32 cur = (chunk&1) ? (u32)SM_BUF : 0u;
        const u32 nxt = (chunk&1) ? 0u : (u32)SM_BUF;
        STSB(cur);
        if (chunk+1 < CHUNKS) LOADB(chunk+1);
        cpasync_wait0();
        __syncthreads();
        if (chunk+1 < CHUNKS){
            CPA(chunk+1, nxt);
            cpasync_commit();
        }

        #pragma unroll
        for (int ks=0; ks<4; ks++){
            u32 ahi[2][4], alo[2][4];
            #pragma unroll
            for (int mt=0;mt<2;mt++){
                int row = wy*32 + mt*16 + (lane&15);
                int kb  = ks*32 + ((lane>>4)<<4);
                u32 off = SW128((u32)(row*128 + kb));
                ldmx4(ahi[mt][0],ahi[mt][1],ahi[mt][2],ahi[mt][3], sb+cur+SM_AHI+off);
                ldmx4(alo[mt][0],alo[mt][1],alo[mt][2],alo[mt][3], sb+cur+SM_ALO+off);
            }
            u32 bhi[7][2], blo[7][2];
            #pragma unroll
            for (int ng=0;ng<3;ng++){
                int row = wx*56 + ng*16 + (lane&7) + ((lane>>4)<<3);
                int kb  = ks*32 + (((lane>>3)&1)<<4);
                u32 off = SW128((u32)(row*128 + kb));
                ldmx4(bhi[2*ng][0],bhi[2*ng][1],bhi[2*ng+1][0],bhi[2*ng+1][1], sb+cur+SM_BHI+off);
                ldmx4(blo[2*ng][0],blo[2*ng][1],blo[2*ng+1][0],blo[2*ng+1][1], sb+cur+SM_BLO+off);
            }
            {
                int row = wx*56 + 48 + (lane&7);
                int kb  = ks*32 + (((lane>>3)&1)<<4);
                u32 off = SW128((u32)(row*128 + kb));
                ldmx2(bhi[6][0],bhi[6][1], sb+cur+SM_BHI+off);
                ldmx2(blo[6][0],blo[6][1], sb+cur+SM_BLO+off);
            }
            #pragma unroll
            for (int mt=0;mt<2;mt++)
                #pragma unroll
                for (int nt=0;nt<7;nt++){
                    mma16816(acc[mt][nt], ahi[mt], bhi[nt]);
                    mma16816(acc[mt][nt], ahi[mt], blo[nt]);
                    mma16816(acc[mt][nt], alo[mt], bhi[nt]);
                }
        }
    }

    {
        const int gid = lane>>2, tig = lane&3;
        #pragma unroll
        for (int mt=0;mt<2;mt++){
            int m = wy*32 + mt*16 + gid;
            #pragma unroll
            for (int nt=0;nt<7;nt++){
                int col = wx*56 + nt*8 + tig*2;
                float c0=acc[mt][nt][0], c1=acc[mt][nt][1], c2=acc[mt][nt][2], c3=acc[mt][nt][3];
                if (lvl==2){
                    int j = col - wx*56;
                    if (j >= 49) continue;
                    float* p0 = cam + ((size_t)((pair*2+wx)*128 + m))*49 + j;
                    float* p1 = p0 + 8*49;
                    p0[0]=c0; p1[0]=c2;
                    if (j+1 < 49){ p0[1]=c1; p1[1]=c3; }
                } else {
                    if (col >= nmax) continue;
                    float* p0 = cam + ((size_t)(b*128 + m))*HW + hw0 + col;
                    float* p1 = p0 + 8*(size_t)HW;
                    float2 v0; v0.x=c0; v0.y=c1; *(float2*)p0=v0;
                    float2 v1; v1.x=c2; v1.y=c3; *(float2*)p1=v1;
                }
            }
        }
    }
}

// ======================================================================
// stats: emb/cert + write pre-split SW128 link tiles directly
// ======================================================================
__device__ __forceinline__ float warp_sum(float v){
    #pragma unroll
    for (int o=16;o;o>>=1) v += __shfl_xor_sync(0xffffffffu,v,o);
    return v;
}

// write the 196-value pattern (7 t-groups) into tiles [tb..tb+3]
__device__ __forceinline__ void write_tiles196(u32* __restrict__ ahi, u32* __restrict__ alo,
                                               int tb, int r, int lane, const float* vals, float inv){
    #pragma unroll
    for (int t=0;t<7;t++){
        int p = lane + t*32;
        float v = (p<196) ? vals[t]*inv : 0.f;
        float vn = __shfl_down_sync(0xffffffffu, v, 1);
        if (!(lane&1)){
            int c = p>>6, kp = (p&63)>>1;
            u32 hi,lo; split_pair(v,vn,hi,lo);
            u32 off = SW128((u32)(r*128 + kp*4))>>2;
            ahi[(size_t)(tb+c)*4096 + off] = hi;
            alo[(size_t)(tb+c)*4096 + off] = lo;
        }
    }
    if (!(lane&1)){          // pad chunk 3, kp 16..31
        int kp = 16 + (lane>>1);
        u32 off = SW128((u32)(r*128 + kp*4))>>2;
        ahi[(size_t)(tb+3)*4096 + off] = 0;
        alo[(size_t)(tb+3)*4096 + off] = 0;
    }
}

// write the 49-value pattern (2 t-groups, full 32-kp coverage incl. pad)
__device__ __forceinline__ void write_tiles49(u32* __restrict__ ahi, u32* __restrict__ alo,
                                              int tb, int r, int lane, const float* vals, float inv){
    #pragma unroll
    for (int t=0;t<2;t++){
        int p = lane + t*32;
        float v = (p<49) ? vals[t]*inv : 0.f;
        float vn = __shfl_down_sync(0xffffffffu, v, 1);
        if (!(lane&1)){
            int kp = p>>1;
            u32 hi,lo; split_pair(v,vn,hi,lo);
            u32 off = SW128((u32)(r*128 + kp*4))>>2;
            ahi[(size_t)tb*4096 + off] = hi;
            alo[(size_t)tb*4096 + off] = lo;
        }
    }
}

__global__ void __launch_bounds__(256) stats_kernel(const float* __restrict__ bias0,const float* __restrict__ bias1,const float* __restrict__ bias2,float* __restrict__ out){
    const int gw=blockIdx.x*8+(threadIdx.x>>5), lane=threadIdx.x&31;
    const int lvl=gw>>13, row=gw&8191, r=row&127, bq=row>>7;
    if (lvl==0){
        const float* c = g_cam0 + (size_t)row*784;
        float sum=0.f, ssq=0.f;
        for (int i=lane;i<784;i+=32){ float v=c[i]; sum+=v; ssq=fmaf(v,v,ssq); }
        sum=warp_sum(sum); ssq=warp_sum(ssq);
        if (lane==0){
            out[row]=sum*(1.0f/784.0f)+bias0[r];
            float var=(ssq-sum*sum*(1.0f/784.0f))*(1.0f/783.0f);
            out[24576+row]=sqrtf(fmaxf(var,0.0f));
        }
        float pv[7]; float nsq=0.f;
        #pragma unroll
        for (int t=0;t<7;t++){
            int p=lane+t*32; float x=0.f;
            if (p<196){ int oh=p/14, ow=p%14, bs=oh*56+ow*2;
                x=(c[bs]+c[bs+1]+c[bs+28]+c[bs+29])*0.25f; }
            pv[t]=x; nsq=fmaf(x,x,nsq);
        }
        nsq=warp_sum(nsq);
        float inv=1.0f/fmaxf(sqrtf(nsq),1e-12f);
        write_tiles196(g_l0a_hi, g_l0a_lo, bq*4, r, lane, pv, inv);
    } else if (lvl==1){
        const float* c = g_cam1 + (size_t)row*196;
        float v[7]; float sum=0.f, ssq=0.f;
        #pragma unroll
        for (int t=0;t<7;t++){ int i=lane+t*32; float x=(i<196)?c[i]:0.f; v[t]=x; sum+=x; ssq=fmaf(x,x,ssq); }
        sum=warp_sum(sum); ssq=warp_sum(ssq);
        if (lane==0){
            out[8192+row]=sum*(1.0f/196.0f)+bias1[r];
            float var=(ssq-sum*sum*(1.0f/196.0f))*(1.0f/195.0f);
            out[24576+8192+row]=sqrtf(fmaxf(var,0.0f));
        }
        float inv=1.0f/fmaxf(sqrtf(ssq),1e-12f);
        write_tiles196(g_l0b_hi, g_l0b_lo, bq*4, r, lane, v, inv);
        float pv[2]; float nsq=0.f;
        #pragma unroll
        for (int t=0;t<2;t++){
            int p=lane+t*32; float x=0.f;
            if (p<49){ int oh=p/7, ow=p%7, bs=oh*28+ow*2;
                x=(c[bs]+c[bs+1]+c[bs+14]+c[bs+15])*0.25f; }
            pv[t]=x; nsq=fmaf(x,x,nsq);
        }
        nsq=warp_sum(nsq);
        float inv2=1.0f/fmaxf(sqrtf(nsq),1e-12f);
        write_tiles49(g_l1a_hi, g_l1a_lo, bq, r, lane, pv, inv2);
    } else {
        const float* c = g_cam2 + (size_t)row*49;
        float v[2]; float sum=0.f, ssq=0.f;
        #pragma unroll
        for (int t=0;t<2;t++){ int i=lane+t*32; float x=(i<49)?c[i]:0.f; v[t]=x; sum+=x; ssq=fmaf(x,x,ssq); }
        sum=warp_sum(sum); ssq=warp_sum(ssq);
        if (lane==0){
            out[16384+row]=sum*(1.0f/49.0f)+bias2[r];
            float var=(ssq-sum*sum*(1.0f/49.0f))*(1.0f/48.0f);
            out[24576+16384+row]=sqrtf(fmaxf(var,0.0f));
        }
        float inv=1.0f/fmaxf(sqrtf(ssq),1e-12f);
        write_tiles49(g_l1b_hi, g_l1b_lo, bq, r, lane, v, inv);
    }
}

// ======================================================================
// link partials: one (slot) = one 64-k chunk. Grid 320:
//   [0,256): L0, slot = b*4 + c ;  [256,320): L1, b = blk-256.
// Staging = pure cp.async of pre-split tiles. Compute identical to before.
// ======================================================================
#define LK_AHI 0
#define LK_ALO 16384
#define LK_BHI 32768
#define LK_BLO 49152
#define LINK_SMEM_BYTES 65536

__global__ void __launch_bounds__(256,1) link_partial_mma(){
    extern __shared__ char smem[];
    const u32 sb = smem_u32(smem);
    const int tid = threadIdx.x, w = tid>>5, lane = tid&31;
    const int blk = blockIdx.x;

    const u32 *ah,*al,*bh,*bl;
    if (blk < 256){
        ah = g_l0a_hi + (size_t)blk*4096; al = g_l0a_lo + (size_t)blk*4096;
        bh = g_l0b_hi + (size_t)blk*4096; bl = g_l0b_lo + (size_t)blk*4096;
    } else {
        int b = blk - 256;
        ah = g_l1a_hi + (size_t)b*4096; al = g_l1a_lo + (size_t)b*4096;
        bh = g_l1b_hi + (size_t)b*4096; bl = g_l1b_lo + (size_t)b*4096;
    }

    // stage 4 tiles (16KB each) via cp.async
    {
        const char* s0 = (const char*)ah + tid*16;
        const char* s1 = (const char*)al + tid*16;
        const char* s2 = (const char*)bh + tid*16;
        const char* s3 = (const char*)bl + tid*16;
        #pragma unroll
        for (int i=0;i<4;i++){
            cpasync16(sb+LK_AHI+tid*16+i*4096, s0+i*4096);
            cpasync16(sb+LK_ALO+tid*16+i*4096, s1+i*4096);
            cpasync16(sb+LK_BHI+tid*16+i*4096, s2+i*4096);
            cpasync16(sb+LK_BLO+tid*16+i*4096, s3+i*4096);
        }
        cpasync_commit();
        cpasync_wait0();
    }
    __syncthreads();

    const int wy = w&3, wx = w>>2;
    float acc[2][8][4];
    #pragma unroll
    for (int mt=0;mt<2;mt++)
        #pragma unroll
        for (int nt=0;nt<8;nt++)
            #pragma unroll
            for (int q=0;q<4;q++) acc[mt][nt][q]=0.f;

    #pragma unroll
    for (int ks=0; ks<4; ks++){
        u32 ahi[2][4], alo[2][4];
        #pragma unroll
        for (int mt=0;mt<2;mt++){
            int row = wy*32 + mt*16 + (lane&15);
            int kb  = ks*32 + ((lane>>4)<<4);
            u32 off = SW128((u32)(row*128 + kb));
            ldmx4(ahi[mt][0],ahi[mt][1],ahi[mt][2],ahi[mt][3], sb+LK_AHI+off);
            ldmx4(alo[mt][0],alo[mt][1],alo[mt][2],alo[mt][3], sb+LK_ALO+off);
        }
        u32 bhi[8][2], blo[8][2];
        #pragma unroll
        for (int ng=0;ng<4;ng++){
            int row = wx*64 + ng*16 + (lane&7) + ((lane>>4)<<3);
            int kb  = ks*32 + (((lane>>3)&1)<<4);
            u32 off = SW128((u32)(row*128 + kb));
            ldmx4(bhi[2*ng][0],bhi[2*ng][1],bhi[2*ng+1][0],bhi[2*ng+1][1], sb+LK_BHI+off);
            ldmx4(blo[2*ng][0],blo[2*ng][1],blo[2*ng+1][0],blo[2*ng+1][1], sb+LK_BLO+off);
        }
        #pragma unroll
        for (int mt=0;mt<2;mt++)
            #pragma unroll
            for (int nt=0;nt<8;nt++){
                mma16816(acc[mt][nt], ahi[mt], bhi[nt]);
                mma16816(acc[mt][nt], ahi[mt], blo[nt]);
                mma16816(acc[mt][nt], alo[mt], bhi[nt]);
            }
    }

    float* P = g_linkpart + (size_t)blk*16384;
    const int gid = lane>>2, tig = lane&3;
    #pragma unroll
    for (int mt=0;mt<2;mt++){
        int m = wy*32 + mt*16 + gid;
        float* p0 = P + (size_t)m*128;
        float* p1 = p0 + 8*128;
        #pragma unroll
        for (int nt=0;nt<8;nt++){
            int col = wx*64 + nt*8 + tig*2;
            float2 v0; v0.x=acc[mt][nt][0]; v0.y=acc[mt][nt][1]; *(float2*)(p0+col)=v0;
            float2 v1; v1.x=acc[mt][nt][2]; v1.y=acc[mt][nt][3]; *(float2*)(p1+col)=v1;
        }
    }
}

__global__ void __launch_bounds__(256) link_reduce(float* __restrict__ out){
    const int idx=blockIdx.x*256+threadIdx.x;
    const int L=idx>>14, mn=idx&16383;
    const int base = L ? 256 : 0;
    const int cnt  = L ? 64 : 256;
    float s0=0.f,s1=0.f,s2=0.f,s3=0.f;
    for (int p=0;p<cnt;p+=4){
        s0 += g_linkpart[(size_t)(base+p  )*16384 + mn];
        s1 += g_linkpart[(size_t)(base+p+1)*16384 + mn];
        s2 += g_linkpart[(size_t)(base+p+2)*16384 + mn];
        s3 += g_linkpart[(size_t)(base+p+3)*16384 + mn];
    }
    out[49152+idx]=((s0+s1)+(s2+s3))*(1.0f/64.0f);
}

extern "C" void kernel_launch(void* const* d_in, const int* in_sizes, int n_in,
                              void* d_out, int out_size)
{
    const float *f0=nullptr,*f1=nullptr,*f2=nullptr,*w0=nullptr,*w1=nullptr,*w2=nullptr;
    const float *bs[3]={nullptr,nullptr,nullptr};
    int bi=0;
    for (int i=0;i<n_in;i++){
        const float* p=(const float*)d_in[i];
        switch (in_sizes[i]){
            case 64*512*784:  f0=p; break;
            case 64*1024*196: f1=p; break;
            case 64*2048*49:  f2=p; break;
            case 128*512:     w0=p; break;
            case 128*1024:    w1=p; break;
            case 128*2048:    w2=p; break;
            case 128:         if (bi<3) bs[bi++]=p; break;
            default: break;
        }
    }
    if (!f0 && n_in>=9){
        f0=(const float*)d_in[0]; w0=(const float*)d_in[1]; bs[0]=(const float*)d_in[2];
        f1=(const float*)d_in[3]; w1=(const float*)d_in[4]; bs[1]=(const float*)d_in[5];
        f2=(const float*)d_in[6]; w2=(const float*)d_in[7]; bs[2]=(const float*)d_in[8];
    }
    float* out=(float*)d_out;

    cudaFuncSetAttribute(mma_cam_gemm, cudaFuncAttributeMaxDynamicSharedMemorySize, GEMM_SMEM_BYTES);
    cudaFuncSetAttribute(link_partial_mma, cudaFuncAttributeMaxDynamicSharedMemorySize, LINK_SMEM_BYTES);

    wsplit_kernel<<<896, 256>>>(w0, w1, w2);
    mma_cam_gemm<<<608, 256, GEMM_SMEM_BYTES>>>(f0, f1, f2);
    stats_kernel<<<3072, 256>>>(bs[0], bs[1], bs[2], out);
    link_partial_mma<<<320, 256, LINK_SMEM_BYTES>>>();
    link_reduce<<<128, 256>>>(out);
}

// round 13
// speedup vs baseline: 1.0308x; 1.0308x over previous
#include <cuda_runtime.h>
#include <cuda_bf16.h>
#include <math.h>
#include <stdint.h>

typedef unsigned int u32; typedef unsigned long long u64;

__device__ float g_cam0 [64*128*784];
__device__ float g_cam1 [64*128*196];
__device__ float g_cam2 [64*128*49];
__device__ float g_linkpart[128*16384];
__device__ u32   g_whi[229376];   // pre-split, pre-swizzled W tiles (bf16x2 hi)
__device__ u32   g_wlo[229376];   // residual lo
// pre-split SW128 link tiles, written by stats_kernel:
__device__ u32 g_l0a_hi[1048576], g_l0a_lo[1048576];  // cam0 pooled+norm  [b*4+c][4096]
__device__ u32 g_l0b_hi[1048576], g_l0b_lo[1048576];  // cam1 norm         [b*4+c][4096]
__device__ u32 g_l1a_hi[262144],  g_l1a_lo[262144];   // cam1 pooled+norm  [b][4096]
__device__ u32 g_l1b_hi[262144],  g_l1b_lo[262144];   // cam2 norm         [b][4096]

__device__ __forceinline__ u32 smem_u32(const void* p){u32 a;asm("{ .reg .u64 t; cvta.to.shared.u64 t, %1; cvt.u32.u64 %0, t; }":"=r"(a):"l"(p));return a;}
#define SW128(o) ((o) ^ (((o) >> 3) & 0x70))
__device__ __forceinline__ void sts32(u32 a,u32 v){asm volatile("st.shared.b32 [%0], %1;"::"r"(a),"r"(v));}
__device__ __forceinline__ u32 cvt_bf16x2(float a,float b){u32 r;asm("cvt.rn.satfinite.bf16x2.f32 %0, %1, %2;":"=r"(r):"f"(b),"f"(a));return r;}
__device__ __forceinline__ void split_pair(float a,float b,u32& hi,u32& lo){
    hi = cvt_bf16x2(a,b);
    float h0 = __uint_as_float(hi<<16);
    float h1 = __uint_as_float(hi&0xffff0000u);
    lo = cvt_bf16x2(a-h0, b-h1);
}
__device__ __forceinline__ void ldmx4(u32& r0,u32& r1,u32& r2,u32& r3,u32 a){
    asm volatile("ldmatrix.sync.aligned.m8n8.x4.shared.b16 {%0,%1,%2,%3}, [%4];":"=r"(r0),"=r"(r1),"=r"(r2),"=r"(r3):"r"(a));
}
__device__ __forceinline__ void ldmx2(u32& r0,u32& r1,u32 a){
    asm volatile("ldmatrix.sync.aligned.m8n8.x2.shared.b16 {%0,%1}, [%2];":"=r"(r0),"=r"(r1):"r"(a));
}
__device__ __forceinline__ void mma16816(float* c,const u32* a,const u32* b){
    asm volatile("mma.sync.aligned.m16n8k16.row.col.f32.bf16.bf16.f32 {%0,%1,%2,%3},{%4,%5,%6,%7},{%8,%9},{%0,%1,%2,%3};"
    :"+f"(c[0]),"+f"(c[1]),"+f"(c[2]),"+f"(c[3])
    :"r"(a[0]),"r"(a[1]),"r"(a[2]),"r"(a[3]),"r"(b[0]),"r"(b[1]));
}
__device__ __forceinline__ void cpasync16(u32 dst,const void* src){
    asm volatile("cp.async.cg.shared.global [%0], [%1], 16;"::"r"(dst),"l"(src));
}
__device__ __forceinline__ void cpasync_commit(){asm volatile("cp.async.commit_group;":::"memory");}
__device__ __forceinline__ void cpasync_wait0(){asm volatile("cp.async.wait_group 0;":::"memory");}
__device__ __forceinline__ void cpasync_wait1(){asm volatile("cp.async.wait_group 1;":::"memory");}

// ---- W pre-split into swizzled tile images: [level][chunk][4096 u32] ----
__global__ void __launch_bounds__(256) wsplit_kernel(const float* __restrict__ w0,const float* __restrict__ w1,const float* __restrict__ w2){
    int idx = blockIdx.x*256 + threadIdx.x;
    const float* w; int base, CP;
    if (idx < 32768)      { w=w0; base=0;     CP=256;  }
    else if (idx < 98304) { w=w1; base=32768; CP=512;  }
    else if (idx < 229376){ w=w2; base=98304; CP=1024; }
    else return;
    int local = idx - base;
    int r  = local / CP;
    int ck = local % CP;
    int chunk = ck >> 5;
    int kp    = ck & 31;
    float2 v = ((const float2*)w)[(size_t)r*CP + chunk*32 + kp];
    u32 hi,lo; split_pair(v.x,v.y,hi,lo);
    u32 dst = (u32)base + chunk*4096u + (SW128((u32)(r*128 + kp*4))>>2);
    g_whi[dst]=hi; g_wlo[dst]=lo;
}

// ======================================================================
// mma.sync bf16-split CAM GEMM — R9 config (proven best).
// ======================================================================
#define SM_AHI 0
#define SM_ALO 16384
#define SM_BHI 32768
#define SM_BLO 47104
#define SM_BUF 61440
#define GEMM_SMEM_BYTES 122880

__global__ void __launch_bounds__(256,1) mma_cam_gemm(const float* __restrict__ f0,const float* __restrict__ f1,const float* __restrict__ f2){
    extern __shared__ char smem[];
    const u32 sb = smem_u32(smem);
    const int tid = threadIdx.x, w = tid>>5, lane = tid&31;

    const int blk = blockIdx.x;
    int lvl,b,hw0,pair=0;
    if (blk < 32)        { lvl=2; pair=blk; b=0; hw0=0; }
    else if (blk < 160)  { lvl=1; int i=blk-32;  b=i>>1; hw0=(i&1)*112; }
    else                 { lvl=0; int i=blk-160; b=i/7;  hw0=(i%7)*112; }

    const float* fmap; float* cam; int C,HW,CHUNKS,wbase;
    if (lvl==0)      { fmap=f0; cam=g_cam0; C=512;  HW=784; CHUNKS=8;  wbase=0; }
    else if (lvl==1) { fmap=f1; cam=g_cam1; C=1024; HW=196; CHUNKS=16; wbase=32768; }
    else             { fmap=f2; cam=g_cam2; C=2048; HW=49;  CHUNKS=32; wbase=98304; }
    int nmax = HW - hw0; if (nmax > 112) nmax = 112;

    const int wy = w&3, wx = w>>2;
    const int nl  = lane>>2;
    const int kp4 = lane&3;
    const int g0n = w*8 + nl;
    const int g1n = (w+8)*8 + nl;
    const bool hasg1 = (w < 6);

    const float* fsrc[2]; bool okg[2];
    #pragma unroll
    for (int g=0; g<2; g++){
        int n = g ? g1n : g0n;
        bool valid = (g==0) || hasg1;
        int bq, j;
        if (lvl==2){ int q = (n>=56)?1:0; j = n - q*56; bq = pair*2 + q; valid = valid && (j<49); }
        else       { j = n; bq = b; valid = valid && (n < nmax); }
        fsrc[g] = fmap + (size_t)bq*C*HW + hw0 + j;
        okg[g]  = valid;
    }

    float pf[2][8][2];
    #define LOADB(CH) do { \
        int _c0 = (CH)*64; \
        _Pragma("unroll") \
        for (int _g=0;_g<2;_g++){ \
            if (_g==1 && !hasg1) break; \
            const float* _p = fsrc[_g] + (size_t)_c0*HW; \
            bool _ok = okg[_g]; \
            _Pragma("unroll") \
            for (int _i=0;_i<8;_i++){ \
                int _kp = _i*4 + kp4; \
                const float* _q = _p + (size_t)(2*_kp)*HW; \
                pf[_g][_i][0] = _ok ? _q[0]  : 0.0f; \
                pf[_g][_i][1] = _ok ? _q[HW] : 0.0f; \
            } \
        } \
    } while(0)

    #define STSB(BUFO) do { \
        _Pragma("unroll") \
        for (int _g=0;_g<2;_g++){ \
            if (_g==1 && !hasg1) break; \
            int _n = _g ? g1n : g0n; \
            _Pragma("unroll") \
            for (int _i=0;_i<8;_i++){ \
                int _kp = _i*4 + kp4; \
                u32 _hi,_lo; split_pair(pf[_g][_i][0], pf[_g][_i][1], _hi, _lo); \
                u32 _off = SW128((u32)(_n*128 + _kp*4)); \
                sts32(sb+(BUFO)+SM_BHI+_off, _hi); \
                sts32(sb+(BUFO)+SM_BLO+_off, _lo); \
            } \
        } \
    } while(0)

    #define CPA(CH,BUFO) do { \
        const char* _sH = (const char*)(g_whi + wbase + (CH)*4096) + tid*16; \
        const char* _sL = (const char*)(g_wlo + wbase + (CH)*4096) + tid*16; \
        u32 _dH = sb + (BUFO) + SM_AHI + tid*16; \
        u32 _dL = sb + (BUFO) + SM_ALO + tid*16; \
        _Pragma("unroll") \
        for (int _i=0;_i<4;_i++){ \
            cpasync16(_dH + _i*4096, _sH + _i*4096); \
            cpasync16(_dL + _i*4096, _sL + _i*4096); \
        } \
    } while(0)

    float acc[2][7][4];
    #pragma unroll
    for (int mt=0;mt<2;mt++)
        #pragma unroll
        for (int nt=0;nt<7;nt++)
            #pragma unroll
            for (int q=0;q<4;q++) acc[mt][nt][q]=0.f;

    CPA(0, 0u);
    cpasync_commit();
    LOADB(0);

    for (int chunk=0; chunk<CHUNKS; chunk++){
        const u32 cur = (chunk&1) ? (u32)SM_BUF : 0u;
        const u32 nxt = (chunk&1) ? 0u : (u32)SM_BUF;
        STSB(cur);
        if (chunk+1 < CHUNKS) LOADB(chunk+1);
        cpasync_wait0();
        __syncthreads();
        if (chunk+1 < CHUNKS){
            CPA(chunk+1, nxt);
            cpasync_commit();
        }

        #pragma unroll
        for (int ks=0; ks<4; ks++){
            u32 ahi[2][4], alo[2][4];
            #pragma unroll
            for (int mt=0;mt<2;mt++){
                int row = wy*32 + mt*16 + (lane&15);
                int kb  = ks*32 + ((lane>>4)<<4);
                u32 off = SW128((u32)(row*128 + kb));
                ldmx4(ahi[mt][0],ahi[mt][1],ahi[mt][2],ahi[mt][3], sb+cur+SM_AHI+off);
                ldmx4(alo[mt][0],alo[mt][1],alo[mt][2],alo[mt][3], sb+cur+SM_ALO+off);
            }
            u32 bhi[7][2], blo[7][2];
            #pragma unroll
            for (int ng=0;ng<3;ng++){
                int row = wx*56 + ng*16 + (lane&7) + ((lane>>4)<<3);
                int kb  = ks*32 + (((lane>>3)&1)<<4);
                u32 off = SW128((u32)(row*128 + kb));
                ldmx4(bhi[2*ng][0],bhi[2*ng][1],bhi[2*ng+1][0],bhi[2*ng+1][1], sb+cur+SM_BHI+off);
                ldmx4(blo[2*ng][0],blo[2*ng][1],blo[2*ng+1][0],blo[2*ng+1][1], sb+cur+SM_BLO+off);
            }
            {
                int row = wx*56 + 48 + (lane&7);
                int kb  = ks*32 + (((lane>>3)&1)<<4);
                u32 off = SW128((u32)(row*128 + kb));
                ldmx2(bhi[6][0],bhi[6][1], sb+cur+SM_BHI+off);
                ldmx2(blo[6][0],blo[6][1], sb+cur+SM_BLO+off);
            }
            #pragma unroll
            for (int mt=0;mt<2;mt++)
                #pragma unroll
                for (int nt=0;nt<7;nt++){
                    mma16816(acc[mt][nt], ahi[mt], bhi[nt]);
                    mma16816(acc[mt][nt], ahi[mt], blo[nt]);
                    mma16816(acc[mt][nt], alo[mt], bhi[nt]);
                }
        }
    }

    {
        const int gid = lane>>2, tig = lane&3;
        #pragma unroll
        for (int mt=0;mt<2;mt++){
            int m = wy*32 + mt*16 + gid;
            #pragma unroll
            for (int nt=0;nt<7;nt++){
                int col = wx*56 + nt*8 + tig*2;
                float c0=acc[mt][nt][0], c1=acc[mt][nt][1], c2=acc[mt][nt][2], c3=acc[mt][nt][3];
                if (lvl==2){
                    int j = col - wx*56;
                    if (j >= 49) continue;
                    float* p0 = cam + ((size_t)((pair*2+wx)*128 + m))*49 + j;
                    float* p1 = p0 + 8*49;
                    p0[0]=c0; p1[0]=c2;
                    if (j+1 < 49){ p0[1]=c1; p1[1]=c3; }
                } else {
                    if (col >= nmax) continue;
                    float* p0 = cam + ((size_t)(b*128 + m))*HW + hw0 + col;
                    float* p1 = p0 + 8*(size_t)HW;
                    float2 v0; v0.x=c0; v0.y=c1; *(float2*)p0=v0;
                    float2 v1; v1.x=c2; v1.y=c3; *(float2*)p1=v1;
                }
            }
        }
    }
}

// ======================================================================
// stats: emb/cert + write pre-split SW128 link tiles directly
// ======================================================================
__device__ __forceinline__ float warp_sum(float v){
    #pragma unroll
    for (int o=16;o;o>>=1) v += __shfl_xor_sync(0xffffffffu,v,o);
    return v;
}

__device__ __forceinline__ void write_tiles196(u32* __restrict__ ahi, u32* __restrict__ alo,
                                               int tb, int r, int lane, const float* vals, float inv){
    #pragma unroll
    for (int t=0;t<7;t++){
        int p = lane + t*32;
        float v = (p<196) ? vals[t]*inv : 0.f;
        float vn = __shfl_down_sync(0xffffffffu, v, 1);
        if (!(lane&1)){
            int c = p>>6, kp = (p&63)>>1;
            u32 hi,lo; split_pair(v,vn,hi,lo);
            u32 off = SW128((u32)(r*128 + kp*4))>>2;
            ahi[(size_t)(tb+c)*4096 + off] = hi;
            alo[(size_t)(tb+c)*4096 + off] = lo;
        }
    }
    if (!(lane&1)){          // pad chunk 3, kp 16..31
        int kp = 16 + (lane>>1);
        u32 off = SW128((u32)(r*128 + kp*4))>>2;
        ahi[(size_t)(tb+3)*4096 + off] = 0;
        alo[(size_t)(tb+3)*4096 + off] = 0;
    }
}

__device__ __forceinline__ void write_tiles49(u32* __restrict__ ahi, u32* __restrict__ alo,
                                              int tb, int r, int lane, const float* vals, float inv){
    #pragma unroll
    for (int t=0;t<2;t++){
        int p = lane + t*32;
        float v = (p<49) ? vals[t]*inv : 0.f;
        float vn = __shfl_down_sync(0xffffffffu, v, 1);
        if (!(lane&1)){
            int kp = p>>1;
            u32 hi,lo; split_pair(v,vn,hi,lo);
            u32 off = SW128((u32)(r*128 + kp*4))>>2;
            ahi[(size_t)tb*4096 + off] = hi;
            alo[(size_t)tb*4096 + off] = lo;
        }
    }
}

__global__ void __launch_bounds__(256) stats_kernel(const float* __restrict__ bias0,const float* __restrict__ bias1,const float* __restrict__ bias2,float* __restrict__ out){
    const int gw=blockIdx.x*8+(threadIdx.x>>5), lane=threadIdx.x&31;
    const int lvl=gw>>13, row=gw&8191, r=row&127, bq=row>>7;
    if (lvl==0){
        const float* c = g_cam0 + (size_t)row*784;
        float sum=0.f, ssq=0.f;
        for (int i=lane;i<784;i+=32){ float v=c[i]; sum+=v; ssq=fmaf(v,v,ssq); }
        sum=warp_sum(sum); ssq=warp_sum(ssq);
        if (lane==0){
            out[row]=sum*(1.0f/784.0f)+bias0[r];
            float var=(ssq-sum*sum*(1.0f/784.0f))*(1.0f/783.0f);
            out[24576+row]=sqrtf(fmaxf(var,0.0f));
        }
        float pv[7]; float nsq=0.f;
        #pragma unroll
        for (int t=0;t<7;t++){
            int p=lane+t*32; float x=0.f;
            if (p<196){ int oh=p/14, ow=p%14, bs=oh*56+ow*2;
                x=(c[bs]+c[bs+1]+c[bs+28]+c[bs+29])*0.25f; }
            pv[t]=x; nsq=fmaf(x,x,nsq);
        }
        nsq=warp_sum(nsq);
        float inv=1.0f/fmaxf(sqrtf(nsq),1e-12f);
        write_tiles196(g_l0a_hi, g_l0a_lo, bq*4, r, lane, pv, inv);
    } else if (lvl==1){
        const float* c = g_cam1 + (size_t)row*196;
        float v[7]; float sum=0.f, ssq=0.f;
        #pragma unroll
        for (int t=0;t<7;t++){ int i=lane+t*32; float x=(i<196)?c[i]:0.f; v[t]=x; sum+=x; ssq=fmaf(x,x,ssq); }
        sum=warp_sum(sum); ssq=warp_sum(ssq);
        if (lane==0){
            out[8192+row]=sum*(1.0f/196.0f)+bias1[r];
            float var=(ssq-sum*sum*(1.0f/196.0f))*(1.0f/195.0f);
            out[24576+8192+row]=sqrtf(fmaxf(var,0.0f));
        }
        float inv=1.0f/fmaxf(sqrtf(ssq),1e-12f);
        write_tiles196(g_l0b_hi, g_l0b_lo, bq*4, r, lane, v, inv);
        float pv[2]; float nsq=0.f;
        #pragma unroll
        for (int t=0;t<2;t++){
            int p=lane+t*32; float x=0.f;
            if (p<49){ int oh=p/7, ow=p%7, bs=oh*28+ow*2;
                x=(c[bs]+c[bs+1]+c[bs+14]+c[bs+15])*0.25f; }
            pv[t]=x; nsq=fmaf(x,x,nsq);
        }
        nsq=warp_sum(nsq);
        float inv2=1.0f/fmaxf(sqrtf(nsq),1e-12f);
        write_tiles49(g_l1a_hi, g_l1a_lo, bq, r, lane, pv, inv2);
    } else {
        const float* c = g_cam2 + (size_t)row*49;
        float v[2]; float sum=0.f, ssq=0.f;
        #pragma unroll
        for (int t=0;t<2;t++){ int i=lane+t*32; float x=(i<49)?c[i]:0.f; v[t]=x; sum+=x; ssq=fmaf(x,x,ssq); }
        sum=warp_sum(sum); ssq=warp_sum(ssq);
        if (lane==0){
            out[16384+row]=sum*(1.0f/49.0f)+bias2[r];
            float var=(ssq-sum*sum*(1.0f/49.0f))*(1.0f/48.0f);
            out[24576+16384+row]=sqrtf(fmaxf(var,0.0f));
        }
        float inv=1.0f/fmaxf(sqrtf(ssq),1e-12f);
        write_tiles49(g_l1b_hi, g_l1b_lo, bq, r, lane, v, inv);
    }
}

// ======================================================================
// link partials: CTA = (L, batch); accumulates over k-chunks with
// double-buffered cp.async staging. Grid 128: [0,64) L0 (4 chunks),
// [64,128) L1 (1 chunk). Partials: 128 slots.
// ======================================================================
#define LKBUF 65536
#define LINK_SMEM_BYTES 131072

__global__ void __launch_bounds__(256,1) link_partial_mma(){
    extern __shared__ char smem[];
    const u32 sb = smem_u32(smem);
    const int tid = threadIdx.x, w = tid>>5, lane = tid&31;
    const int blk = blockIdx.x;

    const u32 *ah,*al,*bh,*bl; int nc;
    if (blk < 64){
        ah = g_l0a_hi + (size_t)blk*4*4096; al = g_l0a_lo + (size_t)blk*4*4096;
        bh = g_l0b_hi + (size_t)blk*4*4096; bl = g_l0b_lo + (size_t)blk*4*4096;
        nc = 4;
    } else {
        int b = blk - 64;
        ah = g_l1a_hi + (size_t)b*4096; al = g_l1a_lo + (size_t)b*4096;
        bh = g_l1b_hi + (size_t)b*4096; bl = g_l1b_lo + (size_t)b*4096;
        nc = 1;
    }

    // load the 4 tiles of chunk C into buffer BUFO (16KB each, 64KB total)
    #define CPL(C,BUFO) do { \
        const char* _s0 = (const char*)(ah + (size_t)(C)*4096) + tid*16; \
        const char* _s1 = (const char*)(al + (size_t)(C)*4096) + tid*16; \
        const char* _s2 = (const char*)(bh + (size_t)(C)*4096) + tid*16; \
        const char* _s3 = (const char*)(bl + (size_t)(C)*4096) + tid*16; \
        u32 _d = sb + (BUFO) + tid*16; \
        _Pragma("unroll") \
        for (int _i=0;_i<4;_i++){ \
            cpasync16(_d         + _i*4096, _s0 + _i*4096); \
            cpasync16(_d + 16384 + _i*4096, _s1 + _i*4096); \
            cpasync16(_d + 32768 + _i*4096, _s2 + _i*4096); \
            cpasync16(_d + 49152 + _i*4096, _s3 + _i*4096); \
        } \
    } while(0)

    const int wy = w&3, wx = w>>2;
    float acc[2][8][4];
    #pragma unroll
    for (int mt=0;mt<2;mt++)
        #pragma unroll
        for (int nt=0;nt<8;nt++)
            #pragma unroll
            for (int q=0;q<4;q++) acc[mt][nt][q]=0.f;

    CPL(0, 0u);
    cpasync_commit();

    for (int c=0; c<nc; c++){
        const u32 cur = (c&1) ? (u32)LKBUF : 0u;
        if (c+1 < nc){
            CPL(c+1, (c&1) ? 0u : (u32)LKBUF);
            cpasync_commit();
            cpasync_wait1();         // chunk c complete, c+1 may be in flight
        } else {
            cpasync_wait0();
        }
        __syncthreads();

        #pragma unroll
        for (int ks=0; ks<4; ks++){
            u32 ahi[2][4], alo[2][4];
            #pragma unroll
            for (int mt=0;mt<2;mt++){
                int row = wy*32 + mt*16 + (lane&15);
                int kb  = ks*32 + ((lane>>4)<<4);
                u32 off = SW128((u32)(row*128 + kb));
                ldmx4(ahi[mt][0],ahi[mt][1],ahi[mt][2],ahi[mt][3], sb+cur+off);
                ldmx4(alo[mt][0],alo[mt][1],alo[mt][2],alo[mt][3], sb+cur+16384+off);
            }
            u32 bhi[8][2], blo[8][2];
            #pragma unroll
            for (int ng=0;ng<4;ng++){
                int row = wx*64 + ng*16 + (lane&7) + ((lane>>4)<<3);
                int kb  = ks*32 + (((lane>>3)&1)<<4);
                u32 off = SW128((u32)(row*128 + kb));
                ldmx4(bhi[2*ng][0],bhi[2*ng][1],bhi[2*ng+1][0],bhi[2*ng+1][1], sb+cur+32768+off);
                ldmx4(blo[2*ng][0],blo[2*ng][1],blo[2*ng+1][0],blo[2*ng+1][1], sb+cur+49152+off);
            }
            #pragma unroll
            for (int mt=0;mt<2;mt++)
                #pragma unroll
                for (int nt=0;nt<8;nt++){
                    mma16816(acc[mt][nt], ahi[mt], bhi[nt]);
                    mma16816(acc[mt][nt], ahi[mt], blo[nt]);
                    mma16816(acc[mt][nt], alo[mt], bhi[nt]);
                }
        }
        __syncthreads();
    }

    float* P = g_linkpart + (size_t)blk*16384;
    const int gid = lane>>2, tig = lane&3;
    #pragma unroll
    for (int mt=0;mt<2;mt++){
        int m = wy*32 + mt*16 + gid;
        float* p0 = P + (size_t)m*128;
        float* p1 = p0 + 8*128;
        #pragma unroll
        for (int nt=0;nt<8;nt++){
            int col = wx*64 + nt*8 + tig*2;
            float2 v0; v0.x=acc[mt][nt][0]; v0.y=acc[mt][nt][1]; *(float2*)(p0+col)=v0;
            float2 v1; v1.x=acc[mt][nt][2]; v1.y=acc[mt][nt][3]; *(float2*)(p1+col)=v1;
        }
    }
}

__global__ void __launch_bounds__(256) link_reduce(float* __restrict__ out){
    const int idx=blockIdx.x*256+threadIdx.x;
    const int L=idx>>14, mn=idx&16383;
    const int base = L ? 64 : 0;
    float s0=0.f,s1=0.f,s2=0.f,s3=0.f;
    for (int p=0;p<64;p+=4){
        s0 += g_linkpart[(size_t)(base+p  )*16384 + mn];
        s1 += g_linkpart[(size_t)(base+p+1)*16384 + mn];
        s2 += g_linkpart[(size_t)(base+p+2)*16384 + mn];
        s3 += g_linkpart[(size_t)(base+p+3)*16384 + mn];
    }
    out[49152+idx]=((s0+s1)+(s2+s3))*(1.0f/64.0f);
}

extern "C" void kernel_launch(void* const* d_in, const int* in_sizes, int n_in,
                              void* d_out, int out_size)
{
    const float *f0=nullptr,*f1=nullptr,*f2=nullptr,*w0=nullptr,*w1=nullptr,*w2=nullptr;
    const float *bs[3]={nullptr,nullptr,nullptr};
    int bi=0;
    for (int i=0;i<n_in;i++){
        const float* p=(const float*)d_in[i];
        switch (in_sizes[i]){
            case 64*512*784:  f0=p; break;
            case 64*1024*196: f1=p; break;
            case 64*2048*49:  f2=p; break;
            case 128*512:     w0=p; break;
            case 128*1024:    w1=p; break;
            case 128*2048:    w2=p; break;
            case 128:         if (bi<3) bs[bi++]=p; break;
            default: break;
        }
    }
    if (!f0 && n_in>=9){
        f0=(const float*)d_in[0]; w0=(const float*)d_in[1]; bs[0]=(const float*)d_in[2];
        f1=(const float*)d_in[3]; w1=(const float*)d_in[4]; bs[1]=(const float*)d_in[5];
        f2=(const float*)d_in[6]; w2=(const float*)d_in[7]; bs[2]=(const float*)d_in[8];
    }
    float* out=(float*)d_out;

    cudaFuncSetAttribute(mma_cam_gemm, cudaFuncAttributeMaxDynamicSharedMemorySize, GEMM_SMEM_BYTES);
    cudaFuncSetAttribute(link_partial_mma, cudaFuncAttributeMaxDynamicSharedMemorySize, LINK_SMEM_BYTES);

    wsplit_kernel<<<896, 256>>>(w0, w1, w2);
    mma_cam_gemm<<<608, 256, GEMM_SMEM_BYTES>>>(f0, f1, f2);
    stats_kernel<<<3072, 256>>>(bs[0], bs[1], bs[2], out);
    link_partial_mma<<<128, 256, LINK_SMEM_BYTES>>>();
    link_reduce<<<128, 256>>>(out);
}

// round 14
// speedup vs baseline: 1.2327x; 1.1959x over previous
#include <cuda_runtime.h>
#include <cuda_bf16.h>
#include <cuda_fp16.h>
#include <math.h>
#include <stdint.h>

typedef unsigned int u32; typedef unsigned long long u64;

__device__ float g_cam0 [64*128*784];
__device__ float g_cam1 [64*128*196];
__device__ float g_cam2 [64*128*49];
__device__ float g_linkpart[128*16384];
__device__ u32   g_whi[229376];   // fp16x2 hi of W, pre-swizzled tiles
__device__ u32   g_wlo[229376];   // fp16x2 residual lo
// pre-split SW128 link tiles (bf16), written by stats_kernel:
__device__ u32 g_l0a_hi[1048576], g_l0a_lo[1048576];  // cam0 pooled+norm  [b*4+c][4096]
__device__ u32 g_l0b_hi[1048576], g_l0b_lo[1048576];  // cam1 norm         [b*4+c][4096]
__device__ u32 g_l1a_hi[262144],  g_l1a_lo[262144];   // cam1 pooled+norm  [b][4096]
__device__ u32 g_l1b_hi[262144],  g_l1b_lo[262144];   // cam2 norm         [b][4096]

__device__ __forceinline__ u32 smem_u32(const void* p){u32 a;asm("{ .reg .u64 t; cvta.to.shared.u64 t, %1; cvt.u32.u64 %0, t; }":"=r"(a):"l"(p));return a;}
#define SW128(o) ((o) ^ (((o) >> 3) & 0x70))
__device__ __forceinline__ void sts32(u32 a,u32 v){asm volatile("st.shared.b32 [%0], %1;"::"r"(a),"r"(v));}
__device__ __forceinline__ u32 cvt_bf16x2(float a,float b){u32 r;asm("cvt.rn.satfinite.bf16x2.f32 %0, %1, %2;":"=r"(r):"f"(b),"f"(a));return r;}
__device__ __forceinline__ void split_pair(float a,float b,u32& hi,u32& lo){   // bf16 (links)
    hi = cvt_bf16x2(a,b);
    float h0 = __uint_as_float(hi<<16);
    float h1 = __uint_as_float(hi&0xffff0000u);
    lo = cvt_bf16x2(a-h0, b-h1);
}
__device__ __forceinline__ u32 pack_f16x2(float a,float b){
    __half2 h = __floats2half2_rn(a,b);
    return *reinterpret_cast<u32*>(&h);
}
__device__ __forceinline__ void split_pair_f16(float a,float b,u32& hi,u32& lo){
    __half2 h = __floats2half2_rn(a,b);
    float h0 = __low2float(h), h1 = __high2float(h);
    __half2 l = __floats2half2_rn(a-h0, b-h1);
    hi = *reinterpret_cast<u32*>(&h);
    lo = *reinterpret_cast<u32*>(&l);
}
__device__ __forceinline__ void ldmx4(u32& r0,u32& r1,u32& r2,u32& r3,u32 a){
    asm volatile("ldmatrix.sync.aligned.m8n8.x4.shared.b16 {%0,%1,%2,%3}, [%4];":"=r"(r0),"=r"(r1),"=r"(r2),"=r"(r3):"r"(a));
}
__device__ __forceinline__ void ldmx2(u32& r0,u32& r1,u32 a){
    asm volatile("ldmatrix.sync.aligned.m8n8.x2.shared.b16 {%0,%1}, [%2];":"=r"(r0),"=r"(r1):"r"(a));
}
__device__ __forceinline__ void mma16816(float* c,const u32* a,const u32* b){  // bf16
    asm volatile("mma.sync.aligned.m16n8k16.row.col.f32.bf16.bf16.f32 {%0,%1,%2,%3},{%4,%5,%6,%7},{%8,%9},{%0,%1,%2,%3};"
    :"+f"(c[0]),"+f"(c[1]),"+f"(c[2]),"+f"(c[3])
    :"r"(a[0]),"r"(a[1]),"r"(a[2]),"r"(a[3]),"r"(b[0]),"r"(b[1]));
}
__device__ __forceinline__ void mma16816h(float* c,const u32* a,const u32* b){ // fp16
    asm volatile("mma.sync.aligned.m16n8k16.row.col.f32.f16.f16.f32 {%0,%1,%2,%3},{%4,%5,%6,%7},{%8,%9},{%0,%1,%2,%3};"
    :"+f"(c[0]),"+f"(c[1]),"+f"(c[2]),"+f"(c[3])
    :"r"(a[0]),"r"(a[1]),"r"(a[2]),"r"(a[3]),"r"(b[0]),"r"(b[1]));
}
__device__ __forceinline__ void cpasync16(u32 dst,const void* src){
    asm volatile("cp.async.cg.shared.global [%0], [%1], 16;"::"r"(dst),"l"(src));
}
__device__ __forceinline__ void cpasync_commit(){asm volatile("cp.async.commit_group;":::"memory");}
__device__ __forceinline__ void cpasync_wait0(){asm volatile("cp.async.wait_group 0;":::"memory");}
__device__ __forceinline__ void cpasync_wait1(){asm volatile("cp.async.wait_group 1;":::"memory");}

// ---- W pre-split (fp16) into swizzled tile images: [level][chunk][4096 u32] ----
__global__ void __launch_bounds__(256) wsplit_kernel(const float* __restrict__ w0,const float* __restrict__ w1,const float* __restrict__ w2){
    int idx = blockIdx.x*256 + threadIdx.x;
    const float* w; int base, CP;
    if (idx < 32768)      { w=w0; base=0;     CP=256;  }
    else if (idx < 98304) { w=w1; base=32768; CP=512;  }
    else if (idx < 229376){ w=w2; base=98304; CP=1024; }
    else return;
    int local = idx - base;
    int r  = local / CP;
    int ck = local % CP;
    int chunk = ck >> 5;
    int kp    = ck & 31;
    float2 v = ((const float2*)w)[(size_t)r*CP + chunk*32 + kp];
    u32 hi,lo; split_pair_f16(v.x,v.y,hi,lo);
    u32 dst = (u32)base + chunk*4096u + (SW128((u32)(r*128 + kp*4))>>2);
    g_whi[dst]=hi; g_wlo[dst]=lo;
}

// ======================================================================
// fp16-split CAM GEMM: D = (Whi+Wlo) @ fp16(fmap). 2 MMAs per k-step.
// CTA: M=128 x N=112, kc=64; 256 thr, 8 warps (4x2), warp tile 32x56.
// Double-buffered smem; A cp.async for chunk i+1 issued post-barrier.
// lvl2 packs 2 batches per CTA (cols 0-48 = b0, 56-104 = b1).
// ======================================================================
#define SM_AHI 0
#define SM_ALO 16384
#define SM_BHI 32768
#define SM_BUF 47104
#define GEMM_SMEM_BYTES 94208

__global__ void __launch_bounds__(256,1) mma_cam_gemm(const float* __restrict__ f0,const float* __restrict__ f1,const float* __restrict__ f2){
    extern __shared__ char smem[];
    const u32 sb = smem_u32(smem);
    const int tid = threadIdx.x, w = tid>>5, lane = tid&31;

    const int blk = blockIdx.x;
    int lvl,b,hw0,pair=0;
    if (blk < 32)        { lvl=2; pair=blk; b=0; hw0=0; }
    else if (blk < 160)  { lvl=1; int i=blk-32;  b=i>>1; hw0=(i&1)*112; }
    else                 { lvl=0; int i=blk-160; b=i/7;  hw0=(i%7)*112; }

    const float* fmap; float* cam; int C,HW,CHUNKS,wbase;
    if (lvl==0)      { fmap=f0; cam=g_cam0; C=512;  HW=784; CHUNKS=8;  wbase=0; }
    else if (lvl==1) { fmap=f1; cam=g_cam1; C=1024; HW=196; CHUNKS=16; wbase=32768; }
    else             { fmap=f2; cam=g_cam2; C=2048; HW=49;  CHUNKS=32; wbase=98304; }
    int nmax = HW - hw0; if (nmax > 112) nmax = 112;

    const int wy = w&3, wx = w>>2;
    const int nl  = lane>>2;
    const int kp4 = lane&3;
    const int g0n = w*8 + nl;
    const int g1n = (w+8)*8 + nl;
    const bool hasg1 = (w < 6);

    const float* fsrc[2]; bool okg[2];
    #pragma unroll
    for (int g=0; g<2; g++){
        int n = g ? g1n : g0n;
        bool valid = (g==0) || hasg1;
        int bq, j;
        if (lvl==2){ int q = (n>=56)?1:0; j = n - q*56; bq = pair*2 + q; valid = valid && (j<49); }
        else       { j = n; bq = b; valid = valid && (n < nmax); }
        fsrc[g] = fmap + (size_t)bq*C*HW + hw0 + j;
        okg[g]  = valid;
    }

    float pf[2][8][2];
    #define LOADB(CH) do { \
        int _c0 = (CH)*64; \
        _Pragma("unroll") \
        for (int _g=0;_g<2;_g++){ \
            if (_g==1 && !hasg1) break; \
            const float* _p = fsrc[_g] + (size_t)_c0*HW; \
            bool _ok = okg[_g]; \
            _Pragma("unroll") \
            for (int _i=0;_i<8;_i++){ \
                int _kp = _i*4 + kp4; \
                const float* _q = _p + (size_t)(2*_kp)*HW; \
                pf[_g][_i][0] = _ok ? _q[0]  : 0.0f; \
                pf[_g][_i][1] = _ok ? _q[HW] : 0.0f; \
            } \
        } \
    } while(0)

    #define STSB(BUFO) do { \
        _Pragma("unroll") \
        for (int _g=0;_g<2;_g++){ \
            if (_g==1 && !hasg1) break; \
            int _n = _g ? g1n : g0n; \
            _Pragma("unroll") \
            for (int _i=0;_i<8;_i++){ \
                int _kp = _i*4 + kp4; \
                u32 _bb = pack_f16x2(pf[_g][_i][0], pf[_g][_i][1]); \
                u32 _off = SW128((u32)(_n*128 + _kp*4)); \
                sts32(sb+(BUFO)+SM_BHI+_off, _bb); \
            } \
        } \
    } while(0)

    #define CPA(CH,BUFO) do { \
        const char* _sH = (const char*)(g_whi + wbase + (CH)*4096) + tid*16; \
        const char* _sL = (const char*)(g_wlo + wbase + (CH)*4096) + tid*16; \
        u32 _dH = sb + (BUFO) + SM_AHI + tid*16; \
        u32 _dL = sb + (BUFO) + SM_ALO + tid*16; \
        _Pragma("unroll") \
        for (int _i=0;_i<4;_i++){ \
            cpasync16(_dH + _i*4096, _sH + _i*4096); \
            cpasync16(_dL + _i*4096, _sL + _i*4096); \
        } \
    } while(0)

    float acc[2][7][4];
    #pragma unroll
    for (int mt=0;mt<2;mt++)
        #pragma unroll
        for (int nt=0;nt<7;nt++)
            #pragma unroll
            for (int q=0;q<4;q++) acc[mt][nt][q]=0.f;

    CPA(0, 0u);
    cpasync_commit();
    LOADB(0);

    for (int chunk=0; chunk<CHUNKS; chunk++){
        const u32 cur = (chunk&1) ? (u32)SM_BUF : 0u;
        const u32 nxt = (chunk&1) ? 0u : (u32)SM_BUF;
        STSB(cur);
        if (chunk+1 < CHUNKS) LOADB(chunk+1);
        cpasync_wait0();
        __syncthreads();
        if (chunk+1 < CHUNKS){
            CPA(chunk+1, nxt);
            cpasync_commit();
        }

        #pragma unroll
        for (int ks=0; ks<4; ks++){
            u32 ahi[2][4], alo[2][4];
            #pragma unroll
            for (int mt=0;mt<2;mt++){
                int row = wy*32 + mt*16 + (lane&15);
                int kb  = ks*32 + ((lane>>4)<<4);
                u32 off = SW128((u32)(row*128 + kb));
                ldmx4(ahi[mt][0],ahi[mt][1],ahi[mt][2],ahi[mt][3], sb+cur+SM_AHI+off);
                ldmx4(alo[mt][0],alo[mt][1],alo[mt][2],alo[mt][3], sb+cur+SM_ALO+off);
            }
            u32 bhi[7][2];
            #pragma unroll
            for (int ng=0;ng<3;ng++){
                int row = wx*56 + ng*16 + (lane&7) + ((lane>>4)<<3);
                int kb  = ks*32 + (((lane>>3)&1)<<4);
                u32 off = SW128((u32)(row*128 + kb));
                ldmx4(bhi[2*ng][0],bhi[2*ng][1],bhi[2*ng+1][0],bhi[2*ng+1][1], sb+cur+SM_BHI+off);
            }
            {
                int row = wx*56 + 48 + (lane&7);
                int kb  = ks*32 + (((lane>>3)&1)<<4);
                u32 off = SW128((u32)(row*128 + kb));
                ldmx2(bhi[6][0],bhi[6][1], sb+cur+SM_BHI+off);
            }
            #pragma unroll
            for (int mt=0;mt<2;mt++)
                #pragma unroll
                for (int nt=0;nt<7;nt++){
                    mma16816h(acc[mt][nt], ahi[mt], bhi[nt]);
                    mma16816h(acc[mt][nt], alo[mt], bhi[nt]);
                }
        }
    }

    {
        const int gid = lane>>2, tig = lane&3;
        #pragma unroll
        for (int mt=0;mt<2;mt++){
            int m = wy*32 + mt*16 + gid;
            #pragma unroll
            for (int nt=0;nt<7;nt++){
                int col = wx*56 + nt*8 + tig*2;
                float c0=acc[mt][nt][0], c1=acc[mt][nt][1], c2=acc[mt][nt][2], c3=acc[mt][nt][3];
                if (lvl==2){
                    int j = col - wx*56;
                    if (j >= 49) continue;
                    float* p0 = cam + ((size_t)((pair*2+wx)*128 + m))*49 + j;
                    float* p1 = p0 + 8*49;
                    p0[0]=c0; p1[0]=c2;
                    if (j+1 < 49){ p0[1]=c1; p1[1]=c3; }
                } else {
                    if (col >= nmax) continue;
                    float* p0 = cam + ((size_t)(b*128 + m))*HW + hw0 + col;
                    float* p1 = p0 + 8*(size_t)HW;
                    float2 v0; v0.x=c0; v0.y=c1; *(float2*)p0=v0;
                    float2 v1; v1.x=c2; v1.y=c3; *(float2*)p1=v1;
                }
            }
        }
    }
}

// ======================================================================
// stats: emb/cert + write pre-split bf16 SW128 link tiles directly
// ======================================================================
__device__ __forceinline__ float warp_sum(float v){
    #pragma unroll
    for (int o=16;o;o>>=1) v += __shfl_xor_sync(0xffffffffu,v,o);
    return v;
}

__device__ __forceinline__ void write_tiles196(u32* __restrict__ ahi, u32* __restrict__ alo,
                                               int tb, int r, int lane, const float* vals, float inv){
    #pragma unroll
    for (int t=0;t<7;t++){
        int p = lane + t*32;
        float v = (p<196) ? vals[t]*inv : 0.f;
        float vn = __shfl_down_sync(0xffffffffu, v, 1);
        if (!(lane&1)){
            int c = p>>6, kp = (p&63)>>1;
            u32 hi,lo; split_pair(v,vn,hi,lo);
            u32 off = SW128((u32)(r*128 + kp*4))>>2;
            ahi[(size_t)(tb+c)*4096 + off] = hi;
            alo[(size_t)(tb+c)*4096 + off] = lo;
        }
    }
    if (!(lane&1)){          // pad chunk 3, kp 16..31
        int kp = 16 + (lane>>1);
        u32 off = SW128((u32)(r*128 + kp*4))>>2;
        ahi[(size_t)(tb+3)*4096 + off] = 0;
        alo[(size_t)(tb+3)*4096 + off] = 0;
    }
}

__device__ __forceinline__ void write_tiles49(u32* __restrict__ ahi, u32* __restrict__ alo,
                                              int tb, int r, int lane, const float* vals, float inv){
    #pragma unroll
    for (int t=0;t<2;t++){
        int p = lane + t*32;
        float v = (p<49) ? vals[t]*inv : 0.f;
        float vn = __shfl_down_sync(0xffffffffu, v, 1);
        if (!(lane&1)){
            int kp = p>>1;
            u32 hi,lo; split_pair(v,vn,hi,lo);
            u32 off = SW128((u32)(r*128 + kp*4))>>2;
            ahi[(size_t)tb*4096 + off] = hi;
            alo[(size_t)tb*4096 + off] = lo;
        }
    }
}

__global__ void __launch_bounds__(256) stats_kernel(const float* __restrict__ bias0,const float* __restrict__ bias1,const float* __restrict__ bias2,float* __restrict__ out){
    const int gw=blockIdx.x*8+(threadIdx.x>>5), lane=threadIdx.x&31;
    const int lvl=gw>>13, row=gw&8191, r=row&127, bq=row>>7;
    if (lvl==0){
        const float* c = g_cam0 + (size_t)row*784;
        float sum=0.f, ssq=0.f;
        for (int i=lane;i<784;i+=32){ float v=c[i]; sum+=v; ssq=fmaf(v,v,ssq); }
        sum=warp_sum(sum); ssq=warp_sum(ssq);
        if (lane==0){
            out[row]=sum*(1.0f/784.0f)+bias0[r];
            float var=(ssq-sum*sum*(1.0f/784.0f))*(1.0f/783.0f);
            out[24576+row]=sqrtf(fmaxf(var,0.0f));
        }
        float pv[7]; float nsq=0.f;
        #pragma unroll
        for (int t=0;t<7;t++){
            int p=lane+t*32; float x=0.f;
            if (p<196){ int oh=p/14, ow=p%14, bs=oh*56+ow*2;
                x=(c[bs]+c[bs+1]+c[bs+28]+c[bs+29])*0.25f; }
            pv[t]=x; nsq=fmaf(x,x,nsq);
        }
        nsq=warp_sum(nsq);
        float inv=1.0f/fmaxf(sqrtf(nsq),1e-12f);
        write_tiles196(g_l0a_hi, g_l0a_lo, bq*4, r, lane, pv, inv);
    } else if (lvl==1){
        const float* c = g_cam1 + (size_t)row*196;
        float v[7]; float sum=0.f, ssq=0.f;
        #pragma unroll
        for (int t=0;t<7;t++){ int i=lane+t*32; float x=(i<196)?c[i]:0.f; v[t]=x; sum+=x; ssq=fmaf(x,x,ssq); }
        sum=warp_sum(sum); ssq=warp_sum(ssq);
        if (lane==0){
            out[8192+row]=sum*(1.0f/196.0f)+bias1[r];
            float var=(ssq-sum*sum*(1.0f/196.0f))*(1.0f/195.0f);
            out[24576+8192+row]=sqrtf(fmaxf(var,0.0f));
        }
        float inv=1.0f/fmaxf(sqrtf(ssq),1e-12f);
        write_tiles196(g_l0b_hi, g_l0b_lo, bq*4, r, lane, v, inv);
        float pv[2]; float nsq=0.f;
        #pragma unroll
        for (int t=0;t<2;t++){
            int p=lane+t*32; float x=0.f;
            if (p<49){ int oh=p/7, ow=p%7, bs=oh*28+ow*2;
                x=(c[bs]+c[bs+1]+c[bs+14]+c[bs+15])*0.25f; }
            pv[t]=x; nsq=fmaf(x,x,nsq);
        }
        nsq=warp_sum(nsq);
        float inv2=1.0f/fmaxf(sqrtf(nsq),1e-12f);
        write_tiles49(g_l1a_hi, g_l1a_lo, bq, r, lane, pv, inv2);
    } else {
        const float* c = g_cam2 + (size_t)row*49;
        float v[2]; float sum=0.f, ssq=0.f;
        #pragma unroll
        for (int t=0;t<2;t++){ int i=lane+t*32; float x=(i<49)?c[i]:0.f; v[t]=x; sum+=x; ssq=fmaf(x,x,ssq); }
        sum=warp_sum(sum); ssq=warp_sum(ssq);
        if (lane==0){
            out[16384+row]=sum*(1.0f/49.0f)+bias2[r];
            float var=(ssq-sum*sum*(1.0f/49.0f))*(1.0f/48.0f);
            out[24576+16384+row]=sqrtf(fmaxf(var,0.0f));
        }
        float inv=1.0f/fmaxf(sqrtf(ssq),1e-12f);
        write_tiles49(g_l1b_hi, g_l1b_lo, bq, r, lane, v, inv);
    }
}

// ======================================================================
// link partials (bf16 3-term): CTA = (L, batch), accumulates k-chunks,
// double-buffered cp.async. Grid 128. Partials: 128 slots.
// ======================================================================
#define LKBUF 65536
#define LINK_SMEM_BYTES 131072

__global__ void __launch_bounds__(256,1) link_partial_mma(){
    extern __shared__ char smem[];
    const u32 sb = smem_u32(smem);
    const int tid = threadIdx.x, w = tid>>5, lane = tid&31;
    const int blk = blockIdx.x;

    const u32 *ah,*al,*bh,*bl; int nc;
    if (blk < 64){
        ah = g_l0a_hi + (size_t)blk*4*4096; al = g_l0a_lo + (size_t)blk*4*4096;
        bh = g_l0b_hi + (size_t)blk*4*4096; bl = g_l0b_lo + (size_t)blk*4*4096;
        nc = 4;
    } else {
        int b = blk - 64;
        ah = g_l1a_hi + (size_t)b*4096; al = g_l1a_lo + (size_t)b*4096;
        bh = g_l1b_hi + (size_t)b*4096; bl = g_l1b_lo + (size_t)b*4096;
        nc = 1;
    }

    #define CPL(C,BUFO) do { \
        const char* _s0 = (const char*)(ah + (size_t)(C)*4096) + tid*16; \
        const char* _s1 = (const char*)(al + (size_t)(C)*4096) + tid*16; \
        const char* _s2 = (const char*)(bh + (size_t)(C)*4096) + tid*16; \
        const char* _s3 = (const char*)(bl + (size_t)(C)*4096) + tid*16; \
        u32 _d = sb + (BUFO) + tid*16; \
        _Pragma("unroll") \
        for (int _i=0;_i<4;_i++){ \
            cpasync16(_d         + _i*4096, _s0 + _i*4096); \
            cpasync16(_d + 16384 + _i*4096, _s1 + _i*4096); \
            cpasync16(_d + 32768 + _i*4096, _s2 + _i*4096); \
            cpasync16(_d + 49152 + _i*4096, _s3 + _i*4096); \
        } \
    } while(0)

    const int wy = w&3, wx = w>>2;
    float acc[2][8][4];
    #pragma unroll
    for (int mt=0;mt<2;mt++)
        #pragma unroll
        for (int nt=0;nt<8;nt++)
            #pragma unroll
            for (int q=0;q<4;q++) acc[mt][nt][q]=0.f;

    CPL(0, 0u);
    cpasync_commit();

    for (int c=0; c<nc; c++){
        const u32 cur = (c&1) ? (u32)LKBUF : 0u;
        if (c+1 < nc){
            CPL(c+1, (c&1) ? 0u : (u32)LKBUF);
            cpasync_commit();
            cpasync_wait1();
        } else {
            cpasync_wait0();
        }
        __syncthreads();

        #pragma unroll
        for (int ks=0; ks<4; ks++){
            u32 ahi[2][4], alo[2][4];
            #pragma unroll
            for (int mt=0;mt<2;mt++){
                int row = wy*32 + mt*16 + (lane&15);
                int kb  = ks*32 + ((lane>>4)<<4);
                u32 off = SW128((u32)(row*128 + kb));
                ldmx4(ahi[mt][0],ahi[mt][1],ahi[mt][2],ahi[mt][3], sb+cur+off);
                ldmx4(alo[mt][0],alo[mt][1],alo[mt][2],alo[mt][3], sb+cur+16384+off);
            }
            u32 bhi[8][2], blo[8][2];
            #pragma unroll
            for (int ng=0;ng<4;ng++){
                int row = wx*64 + ng*16 + (lane&7) + ((lane>>4)<<3);
                int kb  = ks*32 + (((lane>>3)&1)<<4);
                u32 off = SW128((u32)(row*128 + kb));
                ldmx4(bhi[2*ng][0],bhi[2*ng][1],bhi[2*ng+1][0],bhi[2*ng+1][1], sb+cur+32768+off);
                ldmx4(blo[2*ng][0],blo[2*ng][1],blo[2*ng+1][0],blo[2*ng+1][1], sb+cur+49152+off);
            }
            #pragma unroll
            for (int mt=0;mt<2;mt++)
                #pragma unroll
                for (int nt=0;nt<8;nt++){
                    mma16816(acc[mt][nt], ahi[mt], bhi[nt]);
                    mma16816(acc[mt][nt], ahi[mt], blo[nt]);
                    mma16816(acc[mt][nt], alo[mt], bhi[nt]);
                }
        }
        __syncthreads();
    }

    float* P = g_linkpart + (size_t)blk*16384;
    const int gid = lane>>2, tig = lane&3;
    #pragma unroll
    for (int mt=0;mt<2;mt++){
        int m = wy*32 + mt*16 + gid;
        float* p0 = P + (size_t)m*128;
        float* p1 = p0 + 8*128;
        #pragma unroll
        for (int nt=0;nt<8;nt++){
            int col = wx*64 + nt*8 + tig*2;
            float2 v0; v0.x=acc[mt][nt][0]; v0.y=acc[mt][nt][1]; *(float2*)(p0+col)=v0;
            float2 v1; v1.x=acc[mt][nt][2]; v1.y=acc[mt][nt][3]; *(float2*)(p1+col)=v1;
        }
    }
}

__global__ void __launch_bounds__(256) link_reduce(float* __restrict__ out){
    const int idx=blockIdx.x*256+threadIdx.x;
    const int L=idx>>14, mn=idx&16383;
    const int base = L ? 64 : 0;
    float s0=0.f,s1=0.f,s2=0.f,s3=0.f;
    for (int p=0;p<64;p+=4){
        s0 += g_linkpart[(size_t)(base+p  )*16384 + mn];
        s1 += g_linkpart[(size_t)(base+p+1)*16384 + mn];
        s2 += g_linkpart[(size_t)(base+p+2)*16384 + mn];
        s3 += g_linkpart[(size_t)(base+p+3)*16384 + mn];
    }
    out[49152+idx]=((s0+s1)+(s2+s3))*(1.0f/64.0f);
}

extern "C" void kernel_launch(void* const* d_in, const int* in_sizes, int n_in,
                              void* d_out, int out_size)
{
    const float *f0=nullptr,*f1=nullptr,*f2=nullptr,*w0=nullptr,*w1=nullptr,*w2=nullptr;
    const float *bs[3]={nullptr,nullptr,nullptr};
    int bi=0;
    for (int i=0;i<n_in;i++){
        const float* p=(const float*)d_in[i];
        switch (in_sizes[i]){
            case 64*512*784:  f0=p; break;
            case 64*1024*196: f1=p; break;
            case 64*2048*49:  f2=p; break;
            case 128*512:     w0=p; break;
            case 128*1024:    w1=p; break;
            case 128*2048:    w2=p; break;
            case 128:         if (bi<3) bs[bi++]=p; break;
            default: break;
        }
    }
    if (!f0 && n_in>=9){
        f0=(const float*)d_in[0]; w0=(const float*)d_in[1]; bs[0]=(const float*)d_in[2];
        f1=(const float*)d_in[3]; w1=(const float*)d_in[4]; bs[1]=(const float*)d_in[5];
        f2=(const float*)d_in[6]; w2=(const float*)d_in[7]; bs[2]=(const float*)d_in[8];
    }
    float* out=(float*)d_out;

    cudaFuncSetAttribute(mma_cam_gemm, cudaFuncAttributeMaxDynamicSharedMemorySize, GEMM_SMEM_BYTES);
    cudaFuncSetAttribute(link_partial_mma, cudaFuncAttributeMaxDynamicSharedMemorySize, LINK_SMEM_BYTES);

    wsplit_kernel<<<896, 256>>>(w0, w1, w2);
    mma_cam_gemm<<<608, 256, GEMM_SMEM_BYTES>>>(f0, f1, f2);
    stats_kernel<<<3072, 256>>>(bs[0], bs[1], bs[2], out);
    link_partial_mma<<<128, 256, LINK_SMEM_BYTES>>>();
    link_reduce<<<128, 256>>>(out);
}

// round 15
// speedup vs baseline: 1.4362x; 1.1651x over previous
#include <cuda_runtime.h>
#include <cuda_bf16.h>
#include <cuda_fp16.h>
#include <math.h>
#include <stdint.h>

typedef unsigned int u32; typedef unsigned long long u64;

__device__ float g_cam0 [64*128*784];
__device__ float g_cam1 [64*128*196];
__device__ float g_cam2 [64*128*49];
__device__ float g_linkpart[128*16384];
__device__ u32   g_whi[229376];   // fp16x2 W, pre-swizzled tiles
// pre-split SW128 link tiles (bf16), written by stats_kernel:
__device__ u32 g_l0a_hi[1048576], g_l0a_lo[1048576];  // cam0 pooled+norm  [b*4+c][4096]
__device__ u32 g_l0b_hi[1048576], g_l0b_lo[1048576];  // cam1 norm         [b*4+c][4096]
__device__ u32 g_l1a_hi[262144],  g_l1a_lo[262144];   // cam1 pooled+norm  [b][4096]
__device__ u32 g_l1b_hi[262144],  g_l1b_lo[262144];   // cam2 norm         [b][4096]

__device__ __forceinline__ u32 smem_u32(const void* p){u32 a;asm("{ .reg .u64 t; cvta.to.shared.u64 t, %1; cvt.u32.u64 %0, t; }":"=r"(a):"l"(p));return a;}
#define SW128(o) ((o) ^ (((o) >> 3) & 0x70))
__device__ __forceinline__ void sts32(u32 a,u32 v){asm volatile("st.shared.b32 [%0], %1;"::"r"(a),"r"(v));}
__device__ __forceinline__ u32 cvt_bf16x2(float a,float b){u32 r;asm("cvt.rn.satfinite.bf16x2.f32 %0, %1, %2;":"=r"(r):"f"(b),"f"(a));return r;}
__device__ __forceinline__ void split_pair(float a,float b,u32& hi,u32& lo){   // bf16 (links)
    hi = cvt_bf16x2(a,b);
    float h0 = __uint_as_float(hi<<16);
    float h1 = __uint_as_float(hi&0xffff0000u);
    lo = cvt_bf16x2(a-h0, b-h1);
}
__device__ __forceinline__ u32 pack_f16x2(float a,float b){
    __half2 h = __floats2half2_rn(a,b);
    return *reinterpret_cast<u32*>(&h);
}
__device__ __forceinline__ void ldmx4(u32& r0,u32& r1,u32& r2,u32& r3,u32 a){
    asm volatile("ldmatrix.sync.aligned.m8n8.x4.shared.b16 {%0,%1,%2,%3}, [%4];":"=r"(r0),"=r"(r1),"=r"(r2),"=r"(r3):"r"(a));
}
__device__ __forceinline__ void ldmx2(u32& r0,u32& r1,u32 a){
    asm volatile("ldmatrix.sync.aligned.m8n8.x2.shared.b16 {%0,%1}, [%2];":"=r"(r0),"=r"(r1):"r"(a));
}
__device__ __forceinline__ void mma16816(float* c,const u32* a,const u32* b){  // bf16
    asm volatile("mma.sync.aligned.m16n8k16.row.col.f32.bf16.bf16.f32 {%0,%1,%2,%3},{%4,%5,%6,%7},{%8,%9},{%0,%1,%2,%3};"
    :"+f"(c[0]),"+f"(c[1]),"+f"(c[2]),"+f"(c[3])
    :"r"(a[0]),"r"(a[1]),"r"(a[2]),"r"(a[3]),"r"(b[0]),"r"(b[1]));
}
__device__ __forceinline__ void mma16816h(float* c,const u32* a,const u32* b){ // fp16
    asm volatile("mma.sync.aligned.m16n8k16.row.col.f32.f16.f16.f32 {%0,%1,%2,%3},{%4,%5,%6,%7},{%8,%9},{%0,%1,%2,%3};"
    :"+f"(c[0]),"+f"(c[1]),"+f"(c[2]),"+f"(c[3])
    :"r"(a[0]),"r"(a[1]),"r"(a[2]),"r"(a[3]),"r"(b[0]),"r"(b[1]));
}
__device__ __forceinline__ void cpasync16(u32 dst,const void* src){
    asm volatile("cp.async.cg.shared.global [%0], [%1], 16;"::"r"(dst),"l"(src));
}
__device__ __forceinline__ void cpasync_commit(){asm volatile("cp.async.commit_group;":::"memory");}
__device__ __forceinline__ void cpasync_wait0(){asm volatile("cp.async.wait_group 0;":::"memory");}
__device__ __forceinline__ void cpasync_wait1(){asm volatile("cp.async.wait_group 1;":::"memory");}

// ---- W -> fp16, pre-swizzled tile images: [level][chunk][4096 u32] ----
__global__ void __launch_bounds__(256) wsplit_kernel(const float* __restrict__ w0,const float* __restrict__ w1,const float* __restrict__ w2){
    int idx = blockIdx.x*256 + threadIdx.x;
    const float* w; int base, CP;
    if (idx < 32768)      { w=w0; base=0;     CP=256;  }
    else if (idx < 98304) { w=w1; base=32768; CP=512;  }
    else if (idx < 229376){ w=w2; base=98304; CP=1024; }
    else return;
    int local = idx - base;
    int r  = local / CP;
    int ck = local % CP;
    int chunk = ck >> 5;
    int kp    = ck & 31;
    float2 v = ((const float2*)w)[(size_t)r*CP + chunk*32 + kp];
    u32 dst = (u32)base + chunk*4096u + (SW128((u32)(r*128 + kp*4))>>2);
    g_whi[dst] = pack_f16x2(v.x, v.y);
}

// ======================================================================
// 1-term fp16 CAM GEMM: D = fp16(W) @ fp16(fmap). 1 MMA per tile.
// CTA: M=128 x N=112, kc=64; 256 thr, 8 warps (4x2), warp tile 32x56.
// Double-buffered smem; A cp.async for chunk i+1 issued post-barrier.
// lvl2 packs 2 batches per CTA (cols 0-48 = b0, 56-104 = b1).
// ======================================================================
#define SM_A 0
#define SM_B 16384
#define SM_BUF 30720
#define GEMM_SMEM_BYTES 61440

__global__ void __launch_bounds__(256,1) mma_cam_gemm(const float* __restrict__ f0,const float* __restrict__ f1,const float* __restrict__ f2){
    extern __shared__ char smem[];
    const u32 sb = smem_u32(smem);
    const int tid = threadIdx.x, w = tid>>5, lane = tid&31;

    const int blk = blockIdx.x;
    int lvl,b,hw0,pair=0;
    if (blk < 32)        { lvl=2; pair=blk; b=0; hw0=0; }
    else if (blk < 160)  { lvl=1; int i=blk-32;  b=i>>1; hw0=(i&1)*112; }
    else                 { lvl=0; int i=blk-160; b=i/7;  hw0=(i%7)*112; }

    const float* fmap; float* cam; int C,HW,CHUNKS,wbase;
    if (lvl==0)      { fmap=f0; cam=g_cam0; C=512;  HW=784; CHUNKS=8;  wbase=0; }
    else if (lvl==1) { fmap=f1; cam=g_cam1; C=1024; HW=196; CHUNKS=16; wbase=32768; }
    else             { fmap=f2; cam=g_cam2; C=2048; HW=49;  CHUNKS=32; wbase=98304; }
    int nmax = HW - hw0; if (nmax > 112) nmax = 112;

    const int wy = w&3, wx = w>>2;
    const int nl  = lane>>2;
    const int kp4 = lane&3;
    const int g0n = w*8 + nl;
    const int g1n = (w+8)*8 + nl;
    const bool hasg1 = (w < 6);

    const float* fsrc[2]; bool okg[2];
    #pragma unroll
    for (int g=0; g<2; g++){
        int n = g ? g1n : g0n;
        bool valid = (g==0) || hasg1;
        int bq, j;
        if (lvl==2){ int q = (n>=56)?1:0; j = n - q*56; bq = pair*2 + q; valid = valid && (j<49); }
        else       { j = n; bq = b; valid = valid && (n < nmax); }
        fsrc[g] = fmap + (size_t)bq*C*HW + hw0 + j;
        okg[g]  = valid;
    }

    float pf[2][8][2];
    #define LOADB(CH) do { \
        int _c0 = (CH)*64; \
        _Pragma("unroll") \
        for (int _g=0;_g<2;_g++){ \
            if (_g==1 && !hasg1) break; \
            const float* _p = fsrc[_g] + (size_t)_c0*HW; \
            bool _ok = okg[_g]; \
            _Pragma("unroll") \
            for (int _i=0;_i<8;_i++){ \
                int _kp = _i*4 + kp4; \
                const float* _q = _p + (size_t)(2*_kp)*HW; \
                pf[_g][_i][0] = _ok ? _q[0]  : 0.0f; \
                pf[_g][_i][1] = _ok ? _q[HW] : 0.0f; \
            } \
        } \
    } while(0)

    #define STSB(BUFO) do { \
        _Pragma("unroll") \
        for (int _g=0;_g<2;_g++){ \
            if (_g==1 && !hasg1) break; \
            int _n = _g ? g1n : g0n; \
            _Pragma("unroll") \
            for (int _i=0;_i<8;_i++){ \
                int _kp = _i*4 + kp4; \
                u32 _bb = pack_f16x2(pf[_g][_i][0], pf[_g][_i][1]); \
                u32 _off = SW128((u32)(_n*128 + _kp*4)); \
                sts32(sb+(BUFO)+SM_B+_off, _bb); \
            } \
        } \
    } while(0)

    #define CPA(CH,BUFO) do { \
        const char* _sH = (const char*)(g_whi + wbase + (CH)*4096) + tid*16; \
        u32 _dH = sb + (BUFO) + SM_A + tid*16; \
        _Pragma("unroll") \
        for (int _i=0;_i<4;_i++) cpasync16(_dH + _i*4096, _sH + _i*4096); \
    } while(0)

    float acc[2][7][4];
    #pragma unroll
    for (int mt=0;mt<2;mt++)
        #pragma unroll
        for (int nt=0;nt<7;nt++)
            #pragma unroll
            for (int q=0;q<4;q++) acc[mt][nt][q]=0.f;

    CPA(0, 0u);
    cpasync_commit();
    LOADB(0);

    for (int chunk=0; chunk<CHUNKS; chunk++){
        const u32 cur = (chunk&1) ? (u32)SM_BUF : 0u;
        const u32 nxt = (chunk&1) ? 0u : (u32)SM_BUF;
        STSB(cur);
        if (chunk+1 < CHUNKS) LOADB(chunk+1);
        cpasync_wait0();
        __syncthreads();
        if (chunk+1 < CHUNKS){
            CPA(chunk+1, nxt);
            cpasync_commit();
        }

        #pragma unroll
        for (int ks=0; ks<4; ks++){
            u32 ahi[2][4];
            #pragma unroll
            for (int mt=0;mt<2;mt++){
                int row = wy*32 + mt*16 + (lane&15);
                int kb  = ks*32 + ((lane>>4)<<4);
                u32 off = SW128((u32)(row*128 + kb));
                ldmx4(ahi[mt][0],ahi[mt][1],ahi[mt][2],ahi[mt][3], sb+cur+SM_A+off);
            }
            u32 bhi[7][2];
            #pragma unroll
            for (int ng=0;ng<3;ng++){
                int row = wx*56 + ng*16 + (lane&7) + ((lane>>4)<<3);
                int kb  = ks*32 + (((lane>>3)&1)<<4);
                u32 off = SW128((u32)(row*128 + kb));
                ldmx4(bhi[2*ng][0],bhi[2*ng][1],bhi[2*ng+1][0],bhi[2*ng+1][1], sb+cur+SM_B+off);
            }
            {
                int row = wx*56 + 48 + (lane&7);
                int kb  = ks*32 + (((lane>>3)&1)<<4);
                u32 off = SW128((u32)(row*128 + kb));
                ldmx2(bhi[6][0],bhi[6][1], sb+cur+SM_B+off);
            }
            #pragma unroll
            for (int mt=0;mt<2;mt++)
                #pragma unroll
                for (int nt=0;nt<7;nt++)
                    mma16816h(acc[mt][nt], ahi[mt], bhi[nt]);
        }
    }

    {
        const int gid = lane>>2, tig = lane&3;
        #pragma unroll
        for (int mt=0;mt<2;mt++){
            int m = wy*32 + mt*16 + gid;
            #pragma unroll
            for (int nt=0;nt<7;nt++){
                int col = wx*56 + nt*8 + tig*2;
                float c0=acc[mt][nt][0], c1=acc[mt][nt][1], c2=acc[mt][nt][2], c3=acc[mt][nt][3];
                if (lvl==2){
                    int j = col - wx*56;
                    if (j >= 49) continue;
                    float* p0 = cam + ((size_t)((pair*2+wx)*128 + m))*49 + j;
                    float* p1 = p0 + 8*49;
                    p0[0]=c0; p1[0]=c2;
                    if (j+1 < 49){ p0[1]=c1; p1[1]=c3; }
                } else {
                    if (col >= nmax) continue;
                    float* p0 = cam + ((size_t)(b*128 + m))*HW + hw0 + col;
                    float* p1 = p0 + 8*(size_t)HW;
                    float2 v0; v0.x=c0; v0.y=c1; *(float2*)p0=v0;
                    float2 v1; v1.x=c2; v1.y=c3; *(float2*)p1=v1;
                }
            }
        }
    }
}

// ======================================================================
// stats: emb/cert + write pre-split bf16 SW128 link tiles directly
// ======================================================================
__device__ __forceinline__ float warp_sum(float v){
    #pragma unroll
    for (int o=16;o;o>>=1) v += __shfl_xor_sync(0xffffffffu,v,o);
    return v;
}

__device__ __forceinline__ void write_tiles196(u32* __restrict__ ahi, u32* __restrict__ alo,
                                               int tb, int r, int lane, const float* vals, float inv){
    #pragma unroll
    for (int t=0;t<7;t++){
        int p = lane + t*32;
        float v = (p<196) ? vals[t]*inv : 0.f;
        float vn = __shfl_down_sync(0xffffffffu, v, 1);
        if (!(lane&1)){
            int c = p>>6, kp = (p&63)>>1;
            u32 hi,lo; split_pair(v,vn,hi,lo);
            u32 off = SW128((u32)(r*128 + kp*4))>>2;
            ahi[(size_t)(tb+c)*4096 + off] = hi;
            alo[(size_t)(tb+c)*4096 + off] = lo;
        }
    }
    if (!(lane&1)){          // pad chunk 3, kp 16..31
        int kp = 16 + (lane>>1);
        u32 off = SW128((u32)(r*128 + kp*4))>>2;
        ahi[(size_t)(tb+3)*4096 + off] = 0;
        alo[(size_t)(tb+3)*4096 + off] = 0;
    }
}

__device__ __forceinline__ void write_tiles49(u32* __restrict__ ahi, u32* __restrict__ alo,
                                              int tb, int r, int lane, const float* vals, float inv){
    #pragma unroll
    for (int t=0;t<2;t++){
        int p = lane + t*32;
        float v = (p<49) ? vals[t]*inv : 0.f;
        float vn = __shfl_down_sync(0xffffffffu, v, 1);
        if (!(lane&1)){
            int kp = p>>1;
            u32 hi,lo; split_pair(v,vn,hi,lo);
            u32 off = SW128((u32)(r*128 + kp*4))>>2;
            ahi[(size_t)tb*4096 + off] = hi;
            alo[(size_t)tb*4096 + off] = lo;
        }
    }
}

__global__ void __launch_bounds__(256) stats_kernel(const float* __restrict__ bias0,const float* __restrict__ bias1,const float* __restrict__ bias2,float* __restrict__ out){
    const int gw=blockIdx.x*8+(threadIdx.x>>5), lane=threadIdx.x&31;
    const int lvl=gw>>13, row=gw&8191, r=row&127, bq=row>>7;
    if (lvl==0){
        const float* c = g_cam0 + (size_t)row*784;
        float sum=0.f, ssq=0.f;
        for (int i=lane;i<784;i+=32){ float v=c[i]; sum+=v; ssq=fmaf(v,v,ssq); }
        sum=warp_sum(sum); ssq=warp_sum(ssq);
        if (lane==0){
            out[row]=sum*(1.0f/784.0f)+bias0[r];
            float var=(ssq-sum*sum*(1.0f/784.0f))*(1.0f/783.0f);
            out[24576+row]=sqrtf(fmaxf(var,0.0f));
        }
        float pv[7]; float nsq=0.f;
        #pragma unroll
        for (int t=0;t<7;t++){
            int p=lane+t*32; float x=0.f;
            if (p<196){ int oh=p/14, ow=p%14, bs=oh*56+ow*2;
                x=(c[bs]+c[bs+1]+c[bs+28]+c[bs+29])*0.25f; }
            pv[t]=x; nsq=fmaf(x,x,nsq);
        }
        nsq=warp_sum(nsq);
        float inv=1.0f/fmaxf(sqrtf(nsq),1e-12f);
        write_tiles196(g_l0a_hi, g_l0a_lo, bq*4, r, lane, pv, inv);
    } else if (lvl==1){
        const float* c = g_cam1 + (size_t)row*196;
        float v[7]; float sum=0.f, ssq=0.f;
        #pragma unroll
        for (int t=0;t<7;t++){ int i=lane+t*32; float x=(i<196)?c[i]:0.f; v[t]=x; sum+=x; ssq=fmaf(x,x,ssq); }
        sum=warp_sum(sum); ssq=warp_sum(ssq);
        if (lane==0){
            out[8192+row]=sum*(1.0f/196.0f)+bias1[r];
            float var=(ssq-sum*sum*(1.0f/196.0f))*(1.0f/195.0f);
            out[24576+8192+row]=sqrtf(fmaxf(var,0.0f));
        }
        float inv=1.0f/fmaxf(sqrtf(ssq),1e-12f);
        write_tiles196(g_l0b_hi, g_l0b_lo, bq*4, r, lane, v, inv);
        float pv[2]; float nsq=0.f;
        #pragma unroll
        for (int t=0;t<2;t++){
            int p=lane+t*32; float x=0.f;
            if (p<49){ int oh=p/7, ow=p%7, bs=oh*28+ow*2;
                x=(c[bs]+c[bs+1]+c[bs+14]+c[bs+15])*0.25f; }
            pv[t]=x; nsq=fmaf(x,x,nsq);
        }
        nsq=warp_sum(nsq);
        float inv2=1.0f/fmaxf(sqrtf(nsq),1e-12f);
        write_tiles49(g_l1a_hi, g_l1a_lo, bq, r, lane, pv, inv2);
    } else {
        const float* c = g_cam2 + (size_t)row*49;
        float v[2]; float sum=0.f, ssq=0.f;
        #pragma unroll
        for (int t=0;t<2;t++){ int i=lane+t*32; float x=(i<49)?c[i]:0.f; v[t]=x; sum+=x; ssq=fmaf(x,x,ssq); }
        sum=warp_sum(sum); ssq=warp_sum(ssq);
        if (lane==0){
            out[16384+row]=sum*(1.0f/49.0f)+bias2[r];
            float var=(ssq-sum*sum*(1.0f/49.0f))*(1.0f/48.0f);
            out[24576+16384+row]=sqrtf(fmaxf(var,0.0f));
        }
        float inv=1.0f/fmaxf(sqrtf(ssq),1e-12f);
        write_tiles49(g_l1b_hi, g_l1b_lo, bq, r, lane, v, inv);
    }
}

// ======================================================================
// link partials (bf16 3-term): CTA = (L, batch), accumulates k-chunks,
// double-buffered cp.async. Grid 128. Partials: 128 slots.
// ======================================================================
#define LKBUF 65536
#define LINK_SMEM_BYTES 131072

__global__ void __launch_bounds__(256,1) link_partial_mma(){
    extern __shared__ char smem[];
    const u32 sb = smem_u32(smem);
    const int tid = threadIdx.x, w = tid>>5, lane = tid&31;
    const int blk = blockIdx.x;

    const u32 *ah,*al,*bh,*bl; int nc;
    if (blk < 64){
        ah = g_l0a_hi + (size_t)blk*4*4096; al = g_l0a_lo + (size_t)blk*4*4096;
        bh = g_l0b_hi + (size_t)blk*4*4096; bl = g_l0b_lo + (size_t)blk*4*4096;
        nc = 4;
    } else {
        int b = blk - 64;
        ah = g_l1a_hi + (size_t)b*4096; al = g_l1a_lo + (size_t)b*4096;
        bh = g_l1b_hi + (size_t)b*4096; bl = g_l1b_lo + (size_t)b*4096;
        nc = 1;
    }

    #define CPL(C,BUFO) do { \
        const char* _s0 = (const char*)(ah + (size_t)(C)*4096) + tid*16; \
        const char* _s1 = (const char*)(al + (size_t)(C)*4096) + tid*16; \
        const char* _s2 = (const char*)(bh + (size_t)(C)*4096) + tid*16; \
        const char* _s3 = (const char*)(bl + (size_t)(C)*4096) + tid*16; \
        u32 _d = sb + (BUFO) + tid*16; \
        _Pragma("unroll") \
        for (int _i=0;_i<4;_i++){ \
            cpasync16(_d         + _i*4096, _s0 + _i*4096); \
            cpasync16(_d + 16384 + _i*4096, _s1 + _i*4096); \
            cpasync16(_d + 32768 + _i*4096, _s2 + _i*4096); \
            cpasync16(_d + 49152 + _i*4096, _s3 + _i*4096); \
        } \
    } while(0)

    const int wy = w&3, wx = w>>2;
    float acc[2][8][4];
    #pragma unroll
    for (int mt=0;mt<2;mt++)
        #pragma unroll
        for (int nt=0;nt<8;nt++)
            #pragma unroll
            for (int q=0;q<4;q++) acc[mt][nt][q]=0.f;

    CPL(0, 0u);
    cpasync_commit();

    for (int c=0; c<nc; c++){
        const u32 cur = (c&1) ? (u32)LKBUF : 0u;
        if (c+1 < nc){
            CPL(c+1, (c&1) ? 0u : (u32)LKBUF);
            cpasync_commit();
            cpasync_wait1();
        } else {
            cpasync_wait0();
        }
        __syncthreads();

        #pragma unroll
        for (int ks=0; ks<4; ks++){
            u32 ahi[2][4], alo[2][4];
            #pragma unroll
            for (int mt=0;mt<2;mt++){
                int row = wy*32 + mt*16 + (lane&15);
                int kb  = ks*32 + ((lane>>4)<<4);
                u32 off = SW128((u32)(row*128 + kb));
                ldmx4(ahi[mt][0],ahi[mt][1],ahi[mt][2],ahi[mt][3], sb+cur+off);
                ldmx4(alo[mt][0],alo[mt][1],alo[mt][2],alo[mt][3], sb+cur+16384+off);
            }
            u32 bhi[8][2], blo[8][2];
            #pragma unroll
            for (int ng=0;ng<4;ng++){
                int row = wx*64 + ng*16 + (lane&7) + ((lane>>4)<<3);
                int kb  = ks*32 + (((lane>>3)&1)<<4);
                u32 off = SW128((u32)(row*128 + kb));
                ldmx4(bhi[2*ng][0],bhi[2*ng][1],bhi[2*ng+1][0],bhi[2*ng+1][1], sb+cur+32768+off);
                ldmx4(blo[2*ng][0],blo[2*ng][1],blo[2*ng+1][0],blo[2*ng+1][1], sb+cur+49152+off);
            }
            #pragma unroll
            for (int mt=0;mt<2;mt++)
                #pragma unroll
                for (int nt=0;nt<8;nt++){
                    mma16816(acc[mt][nt], ahi[mt], bhi[nt]);
                    mma16816(acc[mt][nt], ahi[mt], blo[nt]);
                    mma16816(acc[mt][nt], alo[mt], bhi[nt]);
                }
        }
        __syncthreads();
    }

    float* P = g_linkpart + (size_t)blk*16384;
    const int gid = lane>>2, tig = lane&3;
    #pragma unroll
    for (int mt=0;mt<2;mt++){
        int m = wy*32 + mt*16 + gid;
        float* p0 = P + (size_t)m*128;
        float* p1 = p0 + 8*128;
        #pragma unroll
        for (int nt=0;nt<8;nt++){
            int col = wx*64 + nt*8 + tig*2;
            float2 v0; v0.x=acc[mt][nt][0]; v0.y=acc[mt][nt][1]; *(float2*)(p0+col)=v0;
            float2 v1; v1.x=acc[mt][nt][2]; v1.y=acc[mt][nt][3]; *(float2*)(p1+col)=v1;
        }
    }
}

__global__ void __launch_bounds__(256) link_reduce(float* __restrict__ out){
    const int idx=blockIdx.x*256+threadIdx.x;
    const int L=idx>>14, mn=idx&16383;
    const int base = L ? 64 : 0;
    float s0=0.f,s1=0.f,s2=0.f,s3=0.f;
    for (int p=0;p<64;p+=4){
        s0 += g_linkpart[(size_t)(base+p  )*16384 + mn];
        s1 += g_linkpart[(size_t)(base+p+1)*16384 + mn];
        s2 += g_linkpart[(size_t)(base+p+2)*16384 + mn];
        s3 += g_linkpart[(size_t)(base+p+3)*16384 + mn];
    }
    out[49152+idx]=((s0+s1)+(s2+s3))*(1.0f/64.0f);
}

extern "C" void kernel_launch(void* const* d_in, const int* in_sizes, int n_in,
                              void* d_out, int out_size)
{
    const float *f0=nullptr,*f1=nullptr,*f2=nullptr,*w0=nullptr,*w1=nullptr,*w2=nullptr;
    const float *bs[3]={nullptr,nullptr,nullptr};
    int bi=0;
    for (int i=0;i<n_in;i++){
        const float* p=(const float*)d_in[i];
        switch (in_sizes[i]){
            case 64*512*784:  f0=p; break;
            case 64*1024*196: f1=p; break;
            case 64*2048*49:  f2=p; break;
            case 128*512:     w0=p; break;
            case 128*1024:    w1=p; break;
            case 128*2048:    w2=p; break;
            case 128:         if (bi<3) bs[bi++]=p; break;
            default: break;
        }
    }
    if (!f0 && n_in>=9){
        f0=(const float*)d_in[0]; w0=(const float*)d_in[1]; bs[0]=(const float*)d_in[2];
        f1=(const float*)d_in[3]; w1=(const float*)d_in[4]; bs[1]=(const float*)d_in[5];
        f2=(const float*)d_in[6]; w2=(const float*)d_in[7]; bs[2]=(const float*)d_in[8];
    }
    float* out=(float*)d_out;

    cudaFuncSetAttribute(mma_cam_gemm, cudaFuncAttributeMaxDynamicSharedMemorySize, GEMM_SMEM_BYTES);
    cudaFuncSetAttribute(link_partial_mma, cudaFuncAttributeMaxDynamicSharedMemorySize, LINK_SMEM_BYTES);

    wsplit_kernel<<<896, 256>>>(w0, w1, w2);
    mma_cam_gemm<<<608, 256, GEMM_SMEM_BYTES>>>(f0, f1, f2);
    stats_kernel<<<3072, 256>>>(bs[0], bs[1], bs[2], out);
    link_partial_mma<<<128, 256, LINK_SMEM_BYTES>>>();
    link_reduce<<<128, 256>>>(out);
}